// round 8
// baseline (speedup 1.0000x reference)
#include <cuda_runtime.h>
#include <mma.h>

using namespace nvcuda;

// Problem constants
#define IN_DIM 512
#define BATCH  1024
#define NN1    25
#define NN2    10
#define D1     128
#define D2     128
#define NCLS   41
#define ROWS1  (BATCH * NN1)        // 25600

// Scratch (device globals; no cudaMalloc allowed)
__device__ float g_agg2[ROWS1 * IN_DIM];   // 52.4 MB
__device__ float g_h2  [ROWS1 * 2 * D2];   // 26.2 MB (raw GEMM out, pre-bias/relu)
__device__ float g_agg1[BATCH * 2 * D2];   // 1 MB

__device__ __forceinline__ void cp16(void* smem_dst, const void* gmem_src) {
    unsigned s = (unsigned)__cvta_generic_to_shared(smem_dst);
    asm volatile("cp.async.cg.shared.global [%0], [%1], 16;\n"
                 :: "r"(s), "l"(gmem_src));
}

// ---------------------------------------------------------------------------
// Kernel A: agg2[i,d] = mean_k flat[i*5120 + d*10 + k], flat = gathered f2 rows
// One block per group of 10 rows. 128 threads. High-MLP coalesced gather.
// ---------------------------------------------------------------------------
__global__ void agg2_kernel(const float* __restrict__ features,
                            const int* __restrict__ ids2) {
    __shared__ float sbuf[NN2 * IN_DIM];   // 5120 floats
    __shared__ int   sIds[NN2];
    const int g   = blockIdx.x;
    const int tid = threadIdx.x;

    if (tid < NN2) sIds[tid] = ids2[g * NN2 + tid];
    __syncthreads();

    float4* s4 = reinterpret_cast<float4*>(sbuf);
#pragma unroll
    for (int j = 0; j < 10; j++) {
        const int i = tid + j * 128;            // 1280 float4 total
        const int r  = i >> 7;
        const int c4 = i & 127;
        s4[i] = *(reinterpret_cast<const float4*>(
                      features + (size_t)sIds[r] * IN_DIM) + c4);
    }
    __syncthreads();

    float* outRow = g_agg2 + (size_t)g * IN_DIM;
#pragma unroll
    for (int j = 0; j < 4; j++) {
        const int d = tid + j * 128;
        const float* p = sbuf + d * NN2;
        float s = 0.f;
#pragma unroll
        for (int k = 0; k < NN2; k++) s += p[k];
        outRow[d] = s * (1.0f / NN2);
    }
}

// ---------------------------------------------------------------------------
// Kernel B: h2_raw = A @ W.  blockIdx.y = half (0: features[ids1]/W2s,
// 1: g_agg2/W2n). BM=64, BN=128 (A read ONCE), BK=16, 3-stage cp.async.
// wmma tf32 16x16x8 fp32-acc; warp tile 16x64 (acc = 4 frags = 32 regs).
// ---------------------------------------------------------------------------
#define BM  64
#define BN  128
#define BK  16
#define NT  (IN_DIM / BK)    // 32 k-tiles
#define LDA 20
#define LDB 132

__global__ __launch_bounds__(256, 3)
void gemm2_kernel(const float* __restrict__ features,
                  const int* __restrict__ ids1,
                  const float* __restrict__ W2s,
                  const float* __restrict__ W2n) {
    __shared__ float sA[3][BM * LDA];   // 15.4 KB
    __shared__ float sB[3][BK * LDB];   // 25.3 KB
    __shared__ int   sIds[BM];

    const int tid  = threadIdx.x;
    const int half = blockIdx.y;
    const int row0 = blockIdx.x * BM;
    const float* __restrict__ W = half ? W2n : W2s;

    if (half == 0 && tid < BM) sIds[tid] = ids1[row0 + tid];
    __syncthreads();

    auto loadTiles = [&](int kt, int buf) {
        // A tile 64x16 = 256 f4 (1/thread)
        {
            const int r  = tid >> 2;
            const int c4 = tid & 3;
            const float* src = half
                ? g_agg2  + (size_t)(row0 + r) * IN_DIM + kt * BK + c4 * 4
                : features + (size_t)sIds[r] * IN_DIM + kt * BK + c4 * 4;
            cp16(&sA[buf][r * LDA + c4 * 4], src);
        }
        // B tile 16x128 = 512 f4 (2/thread)
#pragma unroll
        for (int u = 0; u < 2; u++) {
            const int i  = tid + u * 256;
            const int r  = i >> 5;
            const int c4 = i & 31;
            cp16(&sB[buf][r * LDB + c4 * 4],
                 W + (size_t)(kt * BK + r) * 128 + c4 * 4);
        }
        asm volatile("cp.async.commit_group;\n");
    };

    wmma::fragment<wmma::accumulator, 16, 16, 8, float> acc[4];
#pragma unroll
    for (int j = 0; j < 4; j++) wmma::fill_fragment(acc[j], 0.0f);

    const int warp = tid >> 5;
    const int m0 = (warp >> 1) * 16;   // 0,16,32,48
    const int n0 = (warp & 1) * 64;    // 0,64

    loadTiles(0, 0);
    loadTiles(1, 1);

    for (int kt = 0; kt < NT; kt++) {
        if (kt < NT - 1) asm volatile("cp.async.wait_group 1;\n");
        else             asm volatile("cp.async.wait_group 0;\n");
        __syncthreads();
        if (kt + 2 < NT) loadTiles(kt + 2, (kt + 2) % 3);

        const int cur = kt % 3;
#pragma unroll
        for (int kk = 0; kk < BK; kk += 8) {
            wmma::fragment<wmma::matrix_a, 16, 16, 8, wmma::precision::tf32,
                           wmma::row_major> af;
            wmma::fragment<wmma::matrix_b, 16, 16, 8, wmma::precision::tf32,
                           wmma::row_major> bf;
            wmma::load_matrix_sync(af, &sA[cur][m0 * LDA + kk], LDA);
#pragma unroll
            for (int j = 0; j < 4; j++) {
                wmma::load_matrix_sync(bf, &sB[cur][kk * LDB + n0 + j * 16], LDB);
                wmma::mma_sync(acc[j], af, bf, acc[j]);
            }
        }
        __syncthreads();
    }

#pragma unroll
    for (int j = 0; j < 4; j++)
        wmma::store_matrix_sync(
            g_h2 + (size_t)(row0 + m0) * (2 * D2) + half * D2 + n0 + j * 16,
            acc[j], 2 * D2, wmma::mem_row_major);
}

// ---------------------------------------------------------------------------
// Kernel C: agg1[b,d] = mean_k relu(h2_raw + bias)[flat b*6400 + d*25 + k]
// ---------------------------------------------------------------------------
__global__ void agg1_kernel(const float* __restrict__ b2s,
                            const float* __restrict__ b2n) {
    __shared__ float sbuf[NN1 * 2 * D2];   // 6400 floats
    __shared__ float sbias[2 * D2];
    const int g   = blockIdx.x;
    const int tid = threadIdx.x;   // 256

    sbias[tid] = (tid < D2) ? b2s[tid] : b2n[tid - D2];
    __syncthreads();

    const float4* src4 = reinterpret_cast<const float4*>(
        g_h2 + (size_t)g * NN1 * 2 * D2);
    float4* dst4 = reinterpret_cast<float4*>(sbuf);
    for (int i = tid; i < NN1 * 2 * D2 / 4; i += 256) {
        const int c4 = (i & 63) * 4;
        float4 v = src4[i];
        v.x = fmaxf(v.x + sbias[c4 + 0], 0.f);
        v.y = fmaxf(v.y + sbias[c4 + 1], 0.f);
        v.z = fmaxf(v.z + sbias[c4 + 2], 0.f);
        v.w = fmaxf(v.w + sbias[c4 + 3], 0.f);
        dst4[i] = v;
    }
    __syncthreads();

    const float* p = sbuf + tid * NN1;
    float s = 0.f;
#pragma unroll
    for (int k = 0; k < NN1; k++) s += p[k];
    g_agg1[g * 2 * D2 + tid] = s * (1.0f / NN1);
}

// ---------------------------------------------------------------------------
// Kernel D: 2 rows/block, 256 threads. Each thread owns 4 output cols and
// half the K range (float4 weight loads -> 4x fewer LDG than scalar).
// thread = (r, ks, g): r=tid>>7, ks=(tid>>6)&1, g=tid&63.
//   g<32 : self path, cols 4g..4g+3,  K-half = 256
//   g>=32: neigh path, cols 4(g-32).., K-half = 128
// Partials combined in smem, then classifier (8 warps, shfl reduce).
// ---------------------------------------------------------------------------
#define HRPB 2
__global__ __launch_bounds__(256)
void head_kernel(const float* __restrict__ features,
                 const int* __restrict__ ids0,
                 const float* __restrict__ W1s,
                 const float* __restrict__ b1s,
                 const float* __restrict__ W1n,
                 const float* __restrict__ b1n,
                 const float* __restrict__ Wfc,
                 const float* __restrict__ bfc,
                 float* __restrict__ out) {
    __shared__ float sF0[HRPB * IN_DIM];        // 4 KB
    __shared__ float sA1[HRPB * 2 * D2];        // 2 KB
    __shared__ float sP[2][HRPB * 2 * D1];      // 4 KB partials (per ks)
    __shared__ float sH1[HRPB * 2 * D1];        // 2 KB
    const int row0 = blockIdx.x * HRPB;
    const int tid  = threadIdx.x;               // 256

    {   // F0: 256 f4 (1/thread); A1: 128 f4 (tid<128)
        const int r  = tid >> 7;
        const int c4 = tid & 127;
        const int id = ids0[row0 + r];
        reinterpret_cast<float4*>(sF0)[tid] =
            *(reinterpret_cast<const float4*>(features + (size_t)id * IN_DIM) + c4);
        if (tid < HRPB * 2 * D2 / 4)
            reinterpret_cast<float4*>(sA1)[tid] =
                reinterpret_cast<const float4*>(g_agg1 + (size_t)row0 * 2 * D2)[tid];
    }
    __syncthreads();

    const int r  = tid >> 7;
    const int ks = (tid >> 6) & 1;
    const int g  = tid & 63;
    float4 a = make_float4(0.f, 0.f, 0.f, 0.f);
    if (g < 32) {
        const int c0 = g * 4;
        const int kb = ks * 256;
        const float* f = sF0 + r * IN_DIM + kb;
        const float* w = W1s + (size_t)kb * D1 + c0;
#pragma unroll 4
        for (int k = 0; k < 256; k++) {
            const float fv = f[k];
            const float4 wv = *reinterpret_cast<const float4*>(w + (size_t)k * D1);
            a.x = fmaf(fv, wv.x, a.x);
            a.y = fmaf(fv, wv.y, a.y);
            a.z = fmaf(fv, wv.z, a.z);
            a.w = fmaf(fv, wv.w, a.w);
        }
        *reinterpret_cast<float4*>(&sP[ks][r * 2 * D1 + c0]) = a;
    } else {
        const int c0 = (g - 32) * 4;
        const int kb = ks * 128;
        const float* f = sA1 + r * 2 * D2 + kb;
        const float* w = W1n + (size_t)kb * D1 + c0;
#pragma unroll 4
        for (int k = 0; k < 128; k++) {
            const float fv = f[k];
            const float4 wv = *reinterpret_cast<const float4*>(w + (size_t)k * D1);
            a.x = fmaf(fv, wv.x, a.x);
            a.y = fmaf(fv, wv.y, a.y);
            a.z = fmaf(fv, wv.z, a.z);
            a.w = fmaf(fv, wv.w, a.w);
        }
        *reinterpret_cast<float4*>(&sP[ks][r * 2 * D1 + D1 + c0]) = a;
    }
    __syncthreads();

    for (int i = tid; i < HRPB * 2 * D1; i += 256) {
        const int c = i & 255;
        const float b = (c < D1) ? b1s[c] : b1n[c - D1];
        sH1[i] = sP[0][i] + sP[1][i] + b;
    }
    __syncthreads();

    const int warp = tid >> 5;
    const int lane = tid & 31;
    for (int pc = warp; pc < HRPB * NCLS; pc += 8) {
        const int rr = pc / NCLS;
        const int cc = pc % NCLS;
        float s = 0.f;
#pragma unroll
        for (int k = lane; k < 2 * D1; k += 32)
            s = fmaf(sH1[rr * 2 * D1 + k], Wfc[k * NCLS + cc], s);
#pragma unroll
        for (int off = 16; off > 0; off >>= 1)
            s += __shfl_xor_sync(0xFFFFFFFFu, s, off);
        if (lane == 0) out[(row0 + rr) * NCLS + cc] = s + bfc[cc];
    }
}

// ---------------------------------------------------------------------------
extern "C" void kernel_launch(void* const* d_in, const int* in_sizes, int n_in,
                              void* d_out, int out_size) {
    const float* features = (const float*)d_in[0];
    const int*   ids0     = (const int*)  d_in[1];
    const int*   ids1     = (const int*)  d_in[2];
    const int*   ids2     = (const int*)  d_in[3];
    const float* W2s      = (const float*)d_in[4];
    const float* b2s      = (const float*)d_in[5];
    const float* W2n      = (const float*)d_in[6];
    const float* b2n      = (const float*)d_in[7];
    const float* W1s      = (const float*)d_in[8];
    const float* b1s      = (const float*)d_in[9];
    const float* W1n      = (const float*)d_in[10];
    const float* b1n      = (const float*)d_in[11];
    const float* Wfc      = (const float*)d_in[12];
    const float* bfc      = (const float*)d_in[13];
    float* out = (float*)d_out;

    agg2_kernel<<<ROWS1, 128>>>(features, ids2);
    gemm2_kernel<<<dim3(ROWS1 / BM, 2), 256>>>(features, ids1, W2s, W2n);
    agg1_kernel<<<BATCH, 256>>>(b2s, b2n);
    head_kernel<<<BATCH / HRPB, 256>>>(features, ids0, W1s, b1s, W1n, b1n,
                                       Wfc, bfc, out);
}

// round 9
// speedup vs baseline: 1.0813x; 1.0813x over previous
#include <cuda_runtime.h>
#include <mma.h>

using namespace nvcuda;

// Problem constants
#define IN_DIM 512
#define BATCH  1024
#define NN1    25
#define NN2    10
#define D1     128
#define D2     128
#define NCLS   41
#define ROWS1  (BATCH * NN1)        // 25600

// Scratch (device globals; no cudaMalloc allowed)
__device__ float g_agg2[ROWS1 * IN_DIM];   // 52.4 MB
__device__ float g_h2  [ROWS1 * 2 * D2];   // 26.2 MB (raw GEMM out, pre-bias/relu)
__device__ float g_agg1[BATCH * 2 * D2];   // 1 MB
__device__ float g_h1  [BATCH * 2 * D1];   // 1 MB (raw head GEMM out, pre-bias)

__device__ __forceinline__ void cp16(void* smem_dst, const void* gmem_src) {
    unsigned s = (unsigned)__cvta_generic_to_shared(smem_dst);
    asm volatile("cp.async.cg.shared.global [%0], [%1], 16;\n"
                 :: "r"(s), "l"(gmem_src));
}

// ---------------------------------------------------------------------------
// Kernel A: agg2[i,d] = mean_k flat[i*5120 + d*10 + k], flat = gathered f2 rows
// One block per group of 10 rows. 128 threads. High-MLP coalesced gather.
// ---------------------------------------------------------------------------
__global__ void agg2_kernel(const float* __restrict__ features,
                            const int* __restrict__ ids2) {
    __shared__ float sbuf[NN2 * IN_DIM];   // 5120 floats
    __shared__ int   sIds[NN2];
    const int g   = blockIdx.x;
    const int tid = threadIdx.x;

    if (tid < NN2) sIds[tid] = ids2[g * NN2 + tid];
    __syncthreads();

    float4* s4 = reinterpret_cast<float4*>(sbuf);
#pragma unroll
    for (int j = 0; j < 10; j++) {
        const int i = tid + j * 128;            // 1280 float4 total
        const int r  = i >> 7;
        const int c4 = i & 127;
        s4[i] = *(reinterpret_cast<const float4*>(
                      features + (size_t)sIds[r] * IN_DIM) + c4);
    }
    __syncthreads();

    float* outRow = g_agg2 + (size_t)g * IN_DIM;
#pragma unroll
    for (int j = 0; j < 4; j++) {
        const int d = tid + j * 128;
        const float* p = sbuf + d * NN2;
        float s = 0.f;
#pragma unroll
        for (int k = 0; k < NN2; k++) s += p[k];
        outRow[d] = s * (1.0f / NN2);
    }
}

// ---------------------------------------------------------------------------
// Kernel B: h2_raw = A @ W.  blockIdx.y = half (0: features[ids1]/W2s,
// 1: g_agg2/W2n). BM=64, BN=128 (A read ONCE), BK=16, 3-stage cp.async.
// wmma tf32 16x16x8 fp32-acc; warp tile 16x64 (acc = 4 frags = 32 regs).
// ---------------------------------------------------------------------------
#define BM  64
#define BN  128
#define BK  16
#define NT  (IN_DIM / BK)    // 32 k-tiles
#define LDA 20
#define LDB 132

__global__ __launch_bounds__(256, 3)
void gemm2_kernel(const float* __restrict__ features,
                  const int* __restrict__ ids1,
                  const float* __restrict__ W2s,
                  const float* __restrict__ W2n) {
    __shared__ float sA[3][BM * LDA];   // 15.4 KB
    __shared__ float sB[3][BK * LDB];   // 25.3 KB
    __shared__ int   sIds[BM];

    const int tid  = threadIdx.x;
    const int half = blockIdx.y;
    const int row0 = blockIdx.x * BM;
    const float* __restrict__ W = half ? W2n : W2s;

    if (half == 0 && tid < BM) sIds[tid] = ids1[row0 + tid];
    __syncthreads();

    auto loadTiles = [&](int kt, int buf) {
        {   // A tile 64x16 = 256 f4 (1/thread)
            const int r  = tid >> 2;
            const int c4 = tid & 3;
            const float* src = half
                ? g_agg2  + (size_t)(row0 + r) * IN_DIM + kt * BK + c4 * 4
                : features + (size_t)sIds[r] * IN_DIM + kt * BK + c4 * 4;
            cp16(&sA[buf][r * LDA + c4 * 4], src);
        }
#pragma unroll
        for (int u = 0; u < 2; u++) {   // B tile 16x128 = 512 f4
            const int i  = tid + u * 256;
            const int r  = i >> 5;
            const int c4 = i & 31;
            cp16(&sB[buf][r * LDB + c4 * 4],
                 W + (size_t)(kt * BK + r) * 128 + c4 * 4);
        }
        asm volatile("cp.async.commit_group;\n");
    };

    wmma::fragment<wmma::accumulator, 16, 16, 8, float> acc[4];
#pragma unroll
    for (int j = 0; j < 4; j++) wmma::fill_fragment(acc[j], 0.0f);

    const int warp = tid >> 5;
    const int m0 = (warp >> 1) * 16;   // 0,16,32,48
    const int n0 = (warp & 1) * 64;    // 0,64

    loadTiles(0, 0);
    loadTiles(1, 1);

    for (int kt = 0; kt < NT; kt++) {
        if (kt < NT - 1) asm volatile("cp.async.wait_group 1;\n");
        else             asm volatile("cp.async.wait_group 0;\n");
        __syncthreads();
        if (kt + 2 < NT) loadTiles(kt + 2, (kt + 2) % 3);

        const int cur = kt % 3;
#pragma unroll
        for (int kk = 0; kk < BK; kk += 8) {
            wmma::fragment<wmma::matrix_a, 16, 16, 8, wmma::precision::tf32,
                           wmma::row_major> af;
            wmma::fragment<wmma::matrix_b, 16, 16, 8, wmma::precision::tf32,
                           wmma::row_major> bf;
            wmma::load_matrix_sync(af, &sA[cur][m0 * LDA + kk], LDA);
#pragma unroll
            for (int j = 0; j < 4; j++) {
                wmma::load_matrix_sync(bf, &sB[cur][kk * LDB + n0 + j * 16], LDB);
                wmma::mma_sync(acc[j], af, bf, acc[j]);
            }
        }
        __syncthreads();
    }

#pragma unroll
    for (int j = 0; j < 4; j++)
        wmma::store_matrix_sync(
            g_h2 + (size_t)(row0 + m0) * (2 * D2) + half * D2 + n0 + j * 16,
            acc[j], 2 * D2, wmma::mem_row_major);
}

// ---------------------------------------------------------------------------
// Kernel C: agg1[b,d] = mean_k relu(h2_raw + bias)[flat b*6400 + d*25 + k]
// ---------------------------------------------------------------------------
__global__ void agg1_kernel(const float* __restrict__ b2s,
                            const float* __restrict__ b2n) {
    __shared__ float sbuf[NN1 * 2 * D2];   // 6400 floats
    __shared__ float sbias[2 * D2];
    const int g   = blockIdx.x;
    const int tid = threadIdx.x;   // 256

    sbias[tid] = (tid < D2) ? b2s[tid] : b2n[tid - D2];
    __syncthreads();

    const float4* src4 = reinterpret_cast<const float4*>(
        g_h2 + (size_t)g * NN1 * 2 * D2);
    float4* dst4 = reinterpret_cast<float4*>(sbuf);
    for (int i = tid; i < NN1 * 2 * D2 / 4; i += 256) {
        const int c4 = (i & 63) * 4;
        float4 v = src4[i];
        v.x = fmaxf(v.x + sbias[c4 + 0], 0.f);
        v.y = fmaxf(v.y + sbias[c4 + 1], 0.f);
        v.z = fmaxf(v.z + sbias[c4 + 2], 0.f);
        v.w = fmaxf(v.w + sbias[c4 + 3], 0.f);
        dst4[i] = v;
    }
    __syncthreads();

    const float* p = sbuf + tid * NN1;
    float s = 0.f;
#pragma unroll
    for (int k = 0; k < NN1; k++) s += p[k];
    g_agg1[g * 2 * D2 + tid] = s * (1.0f / NN1);
}

// ---------------------------------------------------------------------------
// Kernel D1: h1_raw = A @ W on tensor cores (same pipeline as gemm2).
//   half 0: A = features[ids0[r]] (K=512), W = W1s -> h1[:, 0:128]
//   half 1: A = g_agg1[r]         (K=256), W = W1n -> h1[:, 128:256]
// Bias folded into the classifier. Grid (1024/64, 2).
// ---------------------------------------------------------------------------
__global__ __launch_bounds__(256, 3)
void head_gemm_kernel(const float* __restrict__ features,
                      const int* __restrict__ ids0,
                      const float* __restrict__ W1s,
                      const float* __restrict__ W1n) {
    __shared__ float sA[3][BM * LDA];
    __shared__ float sB[3][BK * LDB];
    __shared__ int   sIds[BM];

    const int tid  = threadIdx.x;
    const int half = blockIdx.y;
    const int row0 = blockIdx.x * BM;
    const int K    = half ? 2 * D2 : IN_DIM;
    const int nt   = K / BK;
    const float* __restrict__ W = half ? W1n : W1s;

    if (half == 0 && tid < BM) sIds[tid] = ids0[row0 + tid];
    __syncthreads();

    auto loadTiles = [&](int kt, int buf) {
        {
            const int r  = tid >> 2;
            const int c4 = tid & 3;
            const float* src = half
                ? g_agg1  + (size_t)(row0 + r) * (2 * D2) + kt * BK + c4 * 4
                : features + (size_t)sIds[r] * IN_DIM + kt * BK + c4 * 4;
            cp16(&sA[buf][r * LDA + c4 * 4], src);
        }
#pragma unroll
        for (int u = 0; u < 2; u++) {
            const int i  = tid + u * 256;
            const int r  = i >> 5;
            const int c4 = i & 31;
            cp16(&sB[buf][r * LDB + c4 * 4],
                 W + (size_t)(kt * BK + r) * 128 + c4 * 4);
        }
        asm volatile("cp.async.commit_group;\n");
    };

    wmma::fragment<wmma::accumulator, 16, 16, 8, float> acc[4];
#pragma unroll
    for (int j = 0; j < 4; j++) wmma::fill_fragment(acc[j], 0.0f);

    const int warp = tid >> 5;
    const int m0 = (warp >> 1) * 16;
    const int n0 = (warp & 1) * 64;

    loadTiles(0, 0);
    loadTiles(1, 1);

    for (int kt = 0; kt < nt; kt++) {
        if (kt < nt - 1) asm volatile("cp.async.wait_group 1;\n");
        else             asm volatile("cp.async.wait_group 0;\n");
        __syncthreads();
        if (kt + 2 < nt) loadTiles(kt + 2, (kt + 2) % 3);

        const int cur = kt % 3;
#pragma unroll
        for (int kk = 0; kk < BK; kk += 8) {
            wmma::fragment<wmma::matrix_a, 16, 16, 8, wmma::precision::tf32,
                           wmma::row_major> af;
            wmma::fragment<wmma::matrix_b, 16, 16, 8, wmma::precision::tf32,
                           wmma::row_major> bf;
            wmma::load_matrix_sync(af, &sA[cur][m0 * LDA + kk], LDA);
#pragma unroll
            for (int j = 0; j < 4; j++) {
                wmma::load_matrix_sync(bf, &sB[cur][kk * LDB + n0 + j * 16], LDB);
                wmma::mma_sync(acc[j], af, bf, acc[j]);
            }
        }
        __syncthreads();
    }

#pragma unroll
    for (int j = 0; j < 4; j++)
        wmma::store_matrix_sync(
            g_h1 + (size_t)(row0 + m0) * (2 * D1) + half * D1 + n0 + j * 16,
            acc[j], 2 * D1, wmma::mem_row_major);
}

// ---------------------------------------------------------------------------
// Kernel D2: out = (h1_raw + bias) @ Wfc + bfc.
// 8 rows/block, 256 threads. Wfc (256x41 = 42KB) staged in smem once/block.
// ---------------------------------------------------------------------------
#define CRPB 8
__global__ __launch_bounds__(256)
void clf_kernel(const float* __restrict__ b1s,
                const float* __restrict__ b1n,
                const float* __restrict__ Wfc,
                const float* __restrict__ bfc,
                float* __restrict__ out) {
    __shared__ float sW[2 * D1 * NCLS];     // 42 KB
    __shared__ float sH[CRPB * 2 * D1];     // 8 KB
    const int row0 = blockIdx.x * CRPB;
    const int tid  = threadIdx.x;           // 256

    // Stage Wfc (10496 floats = 2624 f4)
    for (int i = tid; i < 2 * D1 * NCLS / 4; i += 256)
        reinterpret_cast<float4*>(sW)[i] =
            reinterpret_cast<const float4*>(Wfc)[i];
    // Stage h1 rows + bias
    for (int i = tid; i < CRPB * 2 * D1; i += 256) {
        const int c = i & 255;
        const float b = (c < D1) ? b1s[c] : b1n[c - D1];
        sH[i] = g_h1[(size_t)row0 * 2 * D1 + i] + b;
    }
    __syncthreads();

    // (row,class) pairs over 8 warps; lanes split K (stride 32), shfl reduce
    const int warp = tid >> 5;
    const int lane = tid & 31;
    for (int pc = warp; pc < CRPB * NCLS; pc += 8) {
        const int r = pc / NCLS;
        const int c = pc % NCLS;
        float s = 0.f;
#pragma unroll
        for (int k = lane; k < 2 * D1; k += 32)
            s = fmaf(sH[r * 2 * D1 + k], sW[k * NCLS + c], s);
#pragma unroll
        for (int off = 16; off > 0; off >>= 1)
            s += __shfl_xor_sync(0xFFFFFFFFu, s, off);
        if (lane == 0) out[(row0 + r) * NCLS + c] = s + bfc[c];
    }
}

// ---------------------------------------------------------------------------
extern "C" void kernel_launch(void* const* d_in, const int* in_sizes, int n_in,
                              void* d_out, int out_size) {
    const float* features = (const float*)d_in[0];
    const int*   ids0     = (const int*)  d_in[1];
    const int*   ids1     = (const int*)  d_in[2];
    const int*   ids2     = (const int*)  d_in[3];
    const float* W2s      = (const float*)d_in[4];
    const float* b2s      = (const float*)d_in[5];
    const float* W2n      = (const float*)d_in[6];
    const float* b2n      = (const float*)d_in[7];
    const float* W1s      = (const float*)d_in[8];
    const float* b1s      = (const float*)d_in[9];
    const float* W1n      = (const float*)d_in[10];
    const float* b1n      = (const float*)d_in[11];
    const float* Wfc      = (const float*)d_in[12];
    const float* bfc      = (const float*)d_in[13];
    float* out = (float*)d_out;

    agg2_kernel<<<ROWS1, 128>>>(features, ids2);
    gemm2_kernel<<<dim3(ROWS1 / BM, 2), 256>>>(features, ids1, W2s, W2n);
    agg1_kernel<<<BATCH, 256>>>(b2s, b2n);
    head_gemm_kernel<<<dim3(BATCH / BM, 2), 256>>>(features, ids0, W1s, W1n);
    clf_kernel<<<BATCH / CRPB, 256>>>(b1s, b1n, Wfc, bfc, out);
}

// round 10
// speedup vs baseline: 1.2086x; 1.1177x over previous
#include <cuda_runtime.h>
#include <mma.h>

using namespace nvcuda;

// Problem constants
#define IN_DIM 512
#define BATCH  1024
#define NN1    25
#define NN2    10
#define D1     128
#define D2     128
#define NCLS   41
#define ROWS1  (BATCH * NN1)        // 25600

// Scratch (device globals; no cudaMalloc allowed)
__device__ float g_agg2[ROWS1 * IN_DIM];        // 52.4 MB
__device__ float g_h2  [ROWS1 * 2 * D2];        // 26.2 MB
__device__ float g_agg1[BATCH * 2 * D2];        // 1 MB
__device__ float g_h1p [4 * BATCH * 2 * D1];    // 4 MB (split-K partials)

__device__ __forceinline__ void cp16(void* smem_dst, const void* gmem_src) {
    unsigned s = (unsigned)__cvta_generic_to_shared(smem_dst);
    asm volatile("cp.async.cg.shared.global [%0], [%1], 16;\n"
                 :: "r"(s), "l"(gmem_src));
}

// ---------------------------------------------------------------------------
// Kernel A: agg2[i,d] = mean_k flat[i*5120 + d*10 + k], flat = gathered f2 rows
// ---------------------------------------------------------------------------
__global__ void agg2_kernel(const float* __restrict__ features,
                            const int* __restrict__ ids2) {
    __shared__ float sbuf[NN2 * IN_DIM];
    __shared__ int   sIds[NN2];
    const int g   = blockIdx.x;
    const int tid = threadIdx.x;

    if (tid < NN2) sIds[tid] = ids2[g * NN2 + tid];
    __syncthreads();

    float4* s4 = reinterpret_cast<float4*>(sbuf);
#pragma unroll
    for (int j = 0; j < 10; j++) {
        const int i = tid + j * 128;
        const int r  = i >> 7;
        const int c4 = i & 127;
        s4[i] = *(reinterpret_cast<const float4*>(
                      features + (size_t)sIds[r] * IN_DIM) + c4);
    }
    __syncthreads();

    float* outRow = g_agg2 + (size_t)g * IN_DIM;
#pragma unroll
    for (int j = 0; j < 4; j++) {
        const int d = tid + j * 128;
        const float* p = sbuf + d * NN2;
        float s = 0.f;
#pragma unroll
        for (int k = 0; k < NN2; k++) s += p[k];
        outRow[d] = s * (1.0f / NN2);
    }
}

// ---------------------------------------------------------------------------
// Kernel B: h2_raw = A @ W. BM=128, BN=128, BK=16, 2-stage cp.async.
// blockIdx.y = half (0: features[ids1]/W2s, 1: g_agg2/W2n).
// 8 warps, warp tile 32x64 (acc[2][4] = 64 regs).
// ---------------------------------------------------------------------------
#define BM2 128
#define BK  16
#define LDA 20
#define LDB 132

__global__ __launch_bounds__(256, 2)
void gemm2_kernel(const float* __restrict__ features,
                  const int* __restrict__ ids1,
                  const float* __restrict__ W2s,
                  const float* __restrict__ W2n) {
    __shared__ float sA[2][BM2 * LDA];   // 20.5 KB
    __shared__ float sB[2][BK * LDB];    // 16.9 KB
    __shared__ int   sIds[BM2];

    const int tid  = threadIdx.x;
    const int half = blockIdx.y;
    const int row0 = blockIdx.x * BM2;
    const float* __restrict__ W = half ? W2n : W2s;
    const int nt = IN_DIM / BK;          // 32

    if (half == 0 && tid < BM2) sIds[tid] = ids1[row0 + tid];
    __syncthreads();

    auto loadTiles = [&](int kt, int buf) {
#pragma unroll
        for (int u = 0; u < 2; u++) {    // A: 128x16 = 512 f4
            const int i  = tid + u * 256;
            const int r  = i >> 2;
            const int c4 = i & 3;
            const float* src = half
                ? g_agg2  + (size_t)(row0 + r) * IN_DIM + kt * BK + c4 * 4
                : features + (size_t)sIds[r] * IN_DIM + kt * BK + c4 * 4;
            cp16(&sA[buf][r * LDA + c4 * 4], src);
        }
#pragma unroll
        for (int u = 0; u < 2; u++) {    // B: 16x128 = 512 f4
            const int i  = tid + u * 256;
            const int r  = i >> 5;
            const int c4 = i & 31;
            cp16(&sB[buf][r * LDB + c4 * 4],
                 W + (size_t)(kt * BK + r) * 128 + c4 * 4);
        }
        asm volatile("cp.async.commit_group;\n");
    };

    wmma::fragment<wmma::accumulator, 16, 16, 8, float> acc[2][4];
#pragma unroll
    for (int i = 0; i < 2; i++)
#pragma unroll
        for (int j = 0; j < 4; j++) wmma::fill_fragment(acc[i][j], 0.0f);

    const int warp = tid >> 5;
    const int m0 = (warp >> 1) * 32;   // 0,32,64,96
    const int n0 = (warp & 1) * 64;    // 0,64

    loadTiles(0, 0);

    for (int kt = 0; kt < nt; kt++) {
        if (kt + 1 < nt) {
            loadTiles(kt + 1, (kt + 1) & 1);
            asm volatile("cp.async.wait_group 1;\n");
        } else {
            asm volatile("cp.async.wait_group 0;\n");
        }
        __syncthreads();

        const int cur = kt & 1;
#pragma unroll
        for (int kk = 0; kk < BK; kk += 8) {
            wmma::fragment<wmma::matrix_a, 16, 16, 8, wmma::precision::tf32,
                           wmma::row_major> af[2];
            wmma::fragment<wmma::matrix_b, 16, 16, 8, wmma::precision::tf32,
                           wmma::row_major> bf;
#pragma unroll
            for (int i = 0; i < 2; i++)
                wmma::load_matrix_sync(af[i], &sA[cur][(m0 + i * 16) * LDA + kk], LDA);
#pragma unroll
            for (int j = 0; j < 4; j++) {
                wmma::load_matrix_sync(bf, &sB[cur][kk * LDB + n0 + j * 16], LDB);
                wmma::mma_sync(acc[0][j], af[0], bf, acc[0][j]);
                wmma::mma_sync(acc[1][j], af[1], bf, acc[1][j]);
            }
        }
        __syncthreads();
    }

#pragma unroll
    for (int i = 0; i < 2; i++)
#pragma unroll
        for (int j = 0; j < 4; j++)
            wmma::store_matrix_sync(
                g_h2 + (size_t)(row0 + m0 + i * 16) * (2 * D2) + half * D2 + n0 + j * 16,
                acc[i][j], 2 * D2, wmma::mem_row_major);
}

// ---------------------------------------------------------------------------
// Kernel C: agg1[b,d] = mean_k relu(h2_raw + bias)[flat b*6400 + d*25 + k]
// ---------------------------------------------------------------------------
__global__ void agg1_kernel(const float* __restrict__ b2s,
                            const float* __restrict__ b2n) {
    __shared__ float sbuf[NN1 * 2 * D2];
    __shared__ float sbias[2 * D2];
    const int g   = blockIdx.x;
    const int tid = threadIdx.x;   // 256

    sbias[tid] = (tid < D2) ? b2s[tid] : b2n[tid - D2];
    __syncthreads();

    const float4* src4 = reinterpret_cast<const float4*>(
        g_h2 + (size_t)g * NN1 * 2 * D2);
    float4* dst4 = reinterpret_cast<float4*>(sbuf);
    for (int i = tid; i < NN1 * 2 * D2 / 4; i += 256) {
        const int c4 = (i & 63) * 4;
        float4 v = src4[i];
        v.x = fmaxf(v.x + sbias[c4 + 0], 0.f);
        v.y = fmaxf(v.y + sbias[c4 + 1], 0.f);
        v.z = fmaxf(v.z + sbias[c4 + 2], 0.f);
        v.w = fmaxf(v.w + sbias[c4 + 3], 0.f);
        dst4[i] = v;
    }
    __syncthreads();

    const float* p = sbuf + tid * NN1;
    float s = 0.f;
#pragma unroll
    for (int k = 0; k < NN1; k++) s += p[k];
    g_agg1[g * 2 * D2 + tid] = s * (1.0f / NN1);
}

// ---------------------------------------------------------------------------
// Kernel D1: split-K head GEMM with 3xTF32 precision recovery.
// grid (16, 2, 4): blockIdx.y = half, blockIdx.z = kz (K-chunk of 128).
//   half 0: A = features[ids0] (K=512, kz 0..3), W = W1s
//   half 1: A = g_agg1 (K=256, kz 0..1; kz 2..3 store zeros), W = W1n
// Partials to g_h1p[kz]; bias folded into clf. BM=64, warp tile 16x64.
// ---------------------------------------------------------------------------
#define HBM 64
#define KCH 128

__global__ __launch_bounds__(256, 3)
void head_gemm_kernel(const float* __restrict__ features,
                      const int* __restrict__ ids0,
                      const float* __restrict__ W1s,
                      const float* __restrict__ W1n) {
    __shared__ float sA[2][HBM * LDA];   // 10.2 KB
    __shared__ float sB[2][BK * LDB];    // 16.9 KB
    __shared__ int   sIds[HBM];

    const int tid  = threadIdx.x;
    const int half = blockIdx.y;
    const int kz   = blockIdx.z;
    const int row0 = blockIdx.x * HBM;
    const int kb   = kz * KCH;
    const bool active = (half == 0) || (kz < 2);
    const float* __restrict__ W = half ? W1n : W1s;
    const int strideA = half ? 2 * D2 : IN_DIM;

    if (half == 0 && tid < HBM) sIds[tid] = ids0[row0 + tid];
    __syncthreads();

    auto loadTiles = [&](int kt, int buf) {
        {   // A: 64x16 = 256 f4
            const int r  = tid >> 2;
            const int c4 = tid & 3;
            const float* src = half
                ? g_agg1  + (size_t)(row0 + r) * strideA + kb + kt * BK + c4 * 4
                : features + (size_t)sIds[r] * strideA + kb + kt * BK + c4 * 4;
            cp16(&sA[buf][r * LDA + c4 * 4], src);
        }
#pragma unroll
        for (int u = 0; u < 2; u++) {   // B: 16x128 = 512 f4
            const int i  = tid + u * 256;
            const int r  = i >> 5;
            const int c4 = i & 31;
            cp16(&sB[buf][r * LDB + c4 * 4],
                 W + (size_t)(kb + kt * BK + r) * 128 + c4 * 4);
        }
        asm volatile("cp.async.commit_group;\n");
    };

    wmma::fragment<wmma::accumulator, 16, 16, 8, float> acc[4];
#pragma unroll
    for (int j = 0; j < 4; j++) wmma::fill_fragment(acc[j], 0.0f);

    const int warp = tid >> 5;
    const int m0 = (warp >> 1) * 16;
    const int n0 = (warp & 1) * 64;

    if (active) {
        const int nt = KCH / BK;   // 8
        loadTiles(0, 0);
        for (int kt = 0; kt < nt; kt++) {
            if (kt + 1 < nt) {
                loadTiles(kt + 1, (kt + 1) & 1);
                asm volatile("cp.async.wait_group 1;\n");
            } else {
                asm volatile("cp.async.wait_group 0;\n");
            }
            __syncthreads();

            const int cur = kt & 1;
#pragma unroll
            for (int kk = 0; kk < BK; kk += 8) {
                wmma::fragment<wmma::matrix_a, 16, 16, 8, wmma::precision::tf32,
                               wmma::row_major> af, afl;
                wmma::load_matrix_sync(af, &sA[cur][m0 * LDA + kk], LDA);
#pragma unroll
                for (int t = 0; t < af.num_elements; t++) {
                    const float hi = wmma::__float_to_tf32(af.x[t]);
                    afl.x[t] = af.x[t] - hi;
                    af.x[t]  = hi;
                }
#pragma unroll
                for (int j = 0; j < 4; j++) {
                    wmma::fragment<wmma::matrix_b, 16, 16, 8, wmma::precision::tf32,
                                   wmma::row_major> bf, bfl;
                    wmma::load_matrix_sync(bf, &sB[cur][kk * LDB + n0 + j * 16], LDB);
#pragma unroll
                    for (int t = 0; t < bf.num_elements; t++) {
                        const float hi = wmma::__float_to_tf32(bf.x[t]);
                        bfl.x[t] = bf.x[t] - hi;
                        bf.x[t]  = hi;
                    }
                    wmma::mma_sync(acc[j], af,  bfl, acc[j]);
                    wmma::mma_sync(acc[j], afl, bf,  acc[j]);
                    wmma::mma_sync(acc[j], af,  bf,  acc[j]);
                }
            }
            __syncthreads();
        }
    }

    float* dst = g_h1p + (size_t)kz * (BATCH * 2 * D1);
#pragma unroll
    for (int j = 0; j < 4; j++)
        wmma::store_matrix_sync(
            dst + (size_t)(row0 + m0) * (2 * D1) + half * D1 + n0 + j * 16,
            acc[j], 2 * D1, wmma::mem_row_major);
}

// ---------------------------------------------------------------------------
// Kernel D2: out = (sum_kz h1p + bias) @ Wfc + bfc.
// 8 rows/block, 256 threads, Wfc staged in smem.
// ---------------------------------------------------------------------------
#define CRPB 8
__global__ __launch_bounds__(256)
void clf_kernel(const float* __restrict__ b1s,
                const float* __restrict__ b1n,
                const float* __restrict__ Wfc,
                const float* __restrict__ bfc,
                float* __restrict__ out) {
    __shared__ float sW[2 * D1 * NCLS];     // 42 KB
    __shared__ float sH[CRPB * 2 * D1];     // 8 KB
    const int row0 = blockIdx.x * CRPB;
    const int tid  = threadIdx.x;           // 256

    for (int i = tid; i < 2 * D1 * NCLS / 4; i += 256)
        reinterpret_cast<float4*>(sW)[i] =
            reinterpret_cast<const float4*>(Wfc)[i];
    for (int i = tid; i < CRPB * 2 * D1; i += 256) {
        const int c = i & 255;
        const float b = (c < D1) ? b1s[c] : b1n[c - D1];
        const size_t off = (size_t)row0 * 2 * D1 + i;
        sH[i] = g_h1p[off]
              + g_h1p[(size_t)(BATCH * 2 * D1) + off]
              + g_h1p[(size_t)(2 * BATCH * 2 * D1) + off]
              + g_h1p[(size_t)(3 * BATCH * 2 * D1) + off] + b;
    }
    __syncthreads();

    const int warp = tid >> 5;
    const int lane = tid & 31;
    for (int pc = warp; pc < CRPB * NCLS; pc += 8) {
        const int r = pc / NCLS;
        const int c = pc % NCLS;
        float s = 0.f;
#pragma unroll
        for (int k = lane; k < 2 * D1; k += 32)
            s = fmaf(sH[r * 2 * D1 + k], sW[k * NCLS + c], s);
#pragma unroll
        for (int off = 16; off > 0; off >>= 1)
            s += __shfl_xor_sync(0xFFFFFFFFu, s, off);
        if (lane == 0) out[(row0 + r) * NCLS + c] = s + bfc[c];
    }
}

// ---------------------------------------------------------------------------
extern "C" void kernel_launch(void* const* d_in, const int* in_sizes, int n_in,
                              void* d_out, int out_size) {
    const float* features = (const float*)d_in[0];
    const int*   ids0     = (const int*)  d_in[1];
    const int*   ids1     = (const int*)  d_in[2];
    const int*   ids2     = (const int*)  d_in[3];
    const float* W2s      = (const float*)d_in[4];
    const float* b2s      = (const float*)d_in[5];
    const float* W2n      = (const float*)d_in[6];
    const float* b2n      = (const float*)d_in[7];
    const float* W1s      = (const float*)d_in[8];
    const float* b1s      = (const float*)d_in[9];
    const float* W1n      = (const float*)d_in[10];
    const float* b1n      = (const float*)d_in[11];
    const float* Wfc      = (const float*)d_in[12];
    const float* bfc      = (const float*)d_in[13];
    float* out = (float*)d_out;

    agg2_kernel<<<ROWS1, 128>>>(features, ids2);
    gemm2_kernel<<<dim3(ROWS1 / BM2, 2), 256>>>(features, ids1, W2s, W2n);
    agg1_kernel<<<BATCH, 256>>>(b2s, b2n);
    head_gemm_kernel<<<dim3(BATCH / HBM, 2, 4), 256>>>(features, ids0, W1s, W1n);
    clf_kernel<<<BATCH / CRPB, 256>>>(b1s, b1n, Wfc, bfc, out);
}

// round 11
// speedup vs baseline: 1.3842x; 1.1453x over previous
#include <cuda_runtime.h>
#include <mma.h>

using namespace nvcuda;

// Problem constants
#define IN_DIM 512
#define BATCH  1024
#define NN1    25
#define NN2    10
#define D1     128
#define D2     128
#define NCLS   41
#define ROWS1  (BATCH * NN1)        // 25600

// Scratch (device globals; no cudaMalloc allowed)
__device__ float g_agg2[ROWS1 * IN_DIM];        // 52.4 MB
__device__ float g_h2  [ROWS1 * 2 * D2];        // 26.2 MB
__device__ float g_agg1[BATCH * 2 * D2];        // 1 MB
__device__ float g_h1p [8 * BATCH * 2 * D1];    // 8 MB (split-K partials)

__device__ __forceinline__ void cp16(void* smem_dst, const void* gmem_src) {
    unsigned s = (unsigned)__cvta_generic_to_shared(smem_dst);
    asm volatile("cp.async.cg.shared.global [%0], [%1], 16;\n"
                 :: "r"(s), "l"(gmem_src));
}

// ---------------------------------------------------------------------------
// Kernel A: agg2[i,d] = mean_k flat[i*5120 + d*10 + k], flat = gathered f2 rows
// cp.async gather: 10 x 16B per thread stream smem-direct (full MLP, no reg
// round trip), one commit/wait.
// ---------------------------------------------------------------------------
__global__ void agg2_kernel(const float* __restrict__ features,
                            const int* __restrict__ ids2) {
    __shared__ __align__(16) float sbuf[NN2 * IN_DIM];
    __shared__ int sIds[NN2];
    const int g   = blockIdx.x;
    const int tid = threadIdx.x;

    if (tid < NN2) sIds[tid] = ids2[g * NN2 + tid];
    __syncthreads();

#pragma unroll
    for (int j = 0; j < 10; j++) {
        const int i  = tid + j * 128;          // 1280 float4 total
        const int r  = i >> 7;
        const int c4 = i & 127;
        cp16(&sbuf[i * 4],
             reinterpret_cast<const float4*>(
                 features + (size_t)sIds[r] * IN_DIM) + c4);
    }
    asm volatile("cp.async.commit_group;\n");
    asm volatile("cp.async.wait_group 0;\n");
    __syncthreads();

    float* outRow = g_agg2 + (size_t)g * IN_DIM;
#pragma unroll
    for (int j = 0; j < 4; j++) {
        const int d = tid + j * 128;
        const float* p = sbuf + d * NN2;
        float s = 0.f;
#pragma unroll
        for (int k = 0; k < NN2; k++) s += p[k];
        outRow[d] = s * (1.0f / NN2);
    }
}

// ---------------------------------------------------------------------------
// Kernel B: h2_raw = A @ W. BM=128, BN=128, BK=16, 4-stage cp.async pipeline
// in DYNAMIC smem (73 KB). blockIdx.y = half (0: features[ids1]/W2s,
// 1: g_agg2/W2n). 8 warps, warp tile 32x64.
// ---------------------------------------------------------------------------
#define BM2 128
#define BK  16
#define LDA 20
#define LDB 132
#define GSTG 4
#define G_A_STG (BM2 * LDA)                     // 2560 floats
#define G_B_STG (BK * LDB)                      // 2112 floats
#define G_SMEM_FLOATS (GSTG * (G_A_STG + G_B_STG))
#define G_SMEM_BYTES  (G_SMEM_FLOATS * 4)       // 74752 B

__global__ __launch_bounds__(256, 2)
void gemm2_kernel(const float* __restrict__ features,
                  const int* __restrict__ ids1,
                  const float* __restrict__ W2s,
                  const float* __restrict__ W2n) {
    extern __shared__ __align__(16) float dsm[];
    float* sA = dsm;                       // [GSTG][BM2*LDA]
    float* sB = dsm + GSTG * G_A_STG;      // [GSTG][BK*LDB]
    __shared__ int sIds[BM2];

    const int tid  = threadIdx.x;
    const int half = blockIdx.y;
    const int row0 = blockIdx.x * BM2;
    const float* __restrict__ W = half ? W2n : W2s;
    const int nt = IN_DIM / BK;            // 32

    if (half == 0 && tid < BM2) sIds[tid] = ids1[row0 + tid];
    __syncthreads();

    auto loadTiles = [&](int kt, int buf) {
        float* a = sA + buf * G_A_STG;
        float* b = sB + buf * G_B_STG;
#pragma unroll
        for (int u = 0; u < 2; u++) {      // A: 128x16 = 512 f4
            const int i  = tid + u * 256;
            const int r  = i >> 2;
            const int c4 = i & 3;
            const float* src = half
                ? g_agg2  + (size_t)(row0 + r) * IN_DIM + kt * BK + c4 * 4
                : features + (size_t)sIds[r] * IN_DIM + kt * BK + c4 * 4;
            cp16(&a[r * LDA + c4 * 4], src);
        }
#pragma unroll
        for (int u = 0; u < 2; u++) {      // B: 16x128 = 512 f4
            const int i  = tid + u * 256;
            const int r  = i >> 5;
            const int c4 = i & 31;
            cp16(&b[r * LDB + c4 * 4],
                 W + (size_t)(kt * BK + r) * 128 + c4 * 4);
        }
        asm volatile("cp.async.commit_group;\n");
    };

    wmma::fragment<wmma::accumulator, 16, 16, 8, float> acc[2][4];
#pragma unroll
    for (int i = 0; i < 2; i++)
#pragma unroll
        for (int j = 0; j < 4; j++) wmma::fill_fragment(acc[i][j], 0.0f);

    const int warp = tid >> 5;
    const int m0 = (warp >> 1) * 32;   // 0,32,64,96
    const int n0 = (warp & 1) * 64;    // 0,64

    loadTiles(0, 0);
    loadTiles(1, 1);
    loadTiles(2, 2);

    for (int kt = 0; kt < nt; kt++) {
        // Ensure tile kt is resident; keep up to GSTG-1 newer groups in flight.
        if (kt + 3 < nt) {
            loadTiles(kt + 3, (kt + 3) & 3);
            asm volatile("cp.async.wait_group 3;\n");
        } else if (kt + 3 == nt) {
            asm volatile("cp.async.wait_group 2;\n");
        } else if (kt + 2 == nt) {
            asm volatile("cp.async.wait_group 1;\n");
        } else {
            asm volatile("cp.async.wait_group 0;\n");
        }
        __syncthreads();

        const int cur = kt & 3;
        const float* a = sA + cur * G_A_STG;
        const float* b = sB + cur * G_B_STG;
#pragma unroll
        for (int kk = 0; kk < BK; kk += 8) {
            wmma::fragment<wmma::matrix_a, 16, 16, 8, wmma::precision::tf32,
                           wmma::row_major> af[2];
            wmma::fragment<wmma::matrix_b, 16, 16, 8, wmma::precision::tf32,
                           wmma::row_major> bf;
#pragma unroll
            for (int i = 0; i < 2; i++)
                wmma::load_matrix_sync(af[i], &a[(m0 + i * 16) * LDA + kk], LDA);
#pragma unroll
            for (int j = 0; j < 4; j++) {
                wmma::load_matrix_sync(bf, &b[kk * LDB + n0 + j * 16], LDB);
                wmma::mma_sync(acc[0][j], af[0], bf, acc[0][j]);
                wmma::mma_sync(acc[1][j], af[1], bf, acc[1][j]);
            }
        }
        __syncthreads();
    }

#pragma unroll
    for (int i = 0; i < 2; i++)
#pragma unroll
        for (int j = 0; j < 4; j++)
            wmma::store_matrix_sync(
                g_h2 + (size_t)(row0 + m0 + i * 16) * (2 * D2) + half * D2 + n0 + j * 16,
                acc[i][j], 2 * D2, wmma::mem_row_major);
}

// ---------------------------------------------------------------------------
// Kernel C: agg1[b,d] = mean_k relu(h2_raw + bias)[flat b*6400 + d*25 + k]
// ---------------------------------------------------------------------------
__global__ void agg1_kernel(const float* __restrict__ b2s,
                            const float* __restrict__ b2n) {
    __shared__ float sbuf[NN1 * 2 * D2];
    __shared__ float sbias[2 * D2];
    const int g   = blockIdx.x;
    const int tid = threadIdx.x;   // 256

    sbias[tid] = (tid < D2) ? b2s[tid] : b2n[tid - D2];
    __syncthreads();

    const float4* src4 = reinterpret_cast<const float4*>(
        g_h2 + (size_t)g * NN1 * 2 * D2);
    float4* dst4 = reinterpret_cast<float4*>(sbuf);
    for (int i = tid; i < NN1 * 2 * D2 / 4; i += 256) {
        const int c4 = (i & 63) * 4;
        float4 v = src4[i];
        v.x = fmaxf(v.x + sbias[c4 + 0], 0.f);
        v.y = fmaxf(v.y + sbias[c4 + 1], 0.f);
        v.z = fmaxf(v.z + sbias[c4 + 2], 0.f);
        v.w = fmaxf(v.w + sbias[c4 + 3], 0.f);
        dst4[i] = v;
    }
    __syncthreads();

    const float* p = sbuf + tid * NN1;
    float s = 0.f;
#pragma unroll
    for (int k = 0; k < NN1; k++) s += p[k];
    g_agg1[g * 2 * D2 + tid] = s * (1.0f / NN1);
}

// ---------------------------------------------------------------------------
// Kernel D1: split-K head GEMM, 3xTF32 precision recovery.
// grid (16, 2, 8): blockIdx.y = half, blockIdx.z = kz (K-chunk of 64).
//   half 0: A = features[ids0] (K=512, kz 0..7), W = W1s
//   half 1: A = g_agg1 (K=256, kz 0..3; kz 4..7 store zeros), W = W1n
// ---------------------------------------------------------------------------
#define HBM 64
#define KCH 64

__global__ __launch_bounds__(256, 3)
void head_gemm_kernel(const float* __restrict__ features,
                      const int* __restrict__ ids0,
                      const float* __restrict__ W1s,
                      const float* __restrict__ W1n) {
    __shared__ float sA[2][HBM * LDA];   // 10.2 KB
    __shared__ float sB[2][BK * LDB];    // 16.9 KB
    __shared__ int   sIds[HBM];

    const int tid  = threadIdx.x;
    const int half = blockIdx.y;
    const int kz   = blockIdx.z;
    const int row0 = blockIdx.x * HBM;
    const int kb   = kz * KCH;
    const bool active = (half == 0) || (kz < 4);
    const float* __restrict__ W = half ? W1n : W1s;
    const int strideA = half ? 2 * D2 : IN_DIM;

    if (half == 0 && tid < HBM) sIds[tid] = ids0[row0 + tid];
    __syncthreads();

    auto loadTiles = [&](int kt, int buf) {
        {   // A: 64x16 = 256 f4
            const int r  = tid >> 2;
            const int c4 = tid & 3;
            const float* src = half
                ? g_agg1  + (size_t)(row0 + r) * strideA + kb + kt * BK + c4 * 4
                : features + (size_t)sIds[r] * strideA + kb + kt * BK + c4 * 4;
            cp16(&sA[buf][r * LDA + c4 * 4], src);
        }
#pragma unroll
        for (int u = 0; u < 2; u++) {   // B: 16x128 = 512 f4
            const int i  = tid + u * 256;
            const int r  = i >> 5;
            const int c4 = i & 31;
            cp16(&sB[buf][r * LDB + c4 * 4],
                 W + (size_t)(kb + kt * BK + r) * 128 + c4 * 4);
        }
        asm volatile("cp.async.commit_group;\n");
    };

    wmma::fragment<wmma::accumulator, 16, 16, 8, float> acc[4];
#pragma unroll
    for (int j = 0; j < 4; j++) wmma::fill_fragment(acc[j], 0.0f);

    const int warp = tid >> 5;
    const int m0 = (warp >> 1) * 16;
    const int n0 = (warp & 1) * 64;

    if (active) {
        const int nt = KCH / BK;   // 4
        loadTiles(0, 0);
        for (int kt = 0; kt < nt; kt++) {
            if (kt + 1 < nt) {
                loadTiles(kt + 1, (kt + 1) & 1);
                asm volatile("cp.async.wait_group 1;\n");
            } else {
                asm volatile("cp.async.wait_group 0;\n");
            }
            __syncthreads();

            const int cur = kt & 1;
#pragma unroll
            for (int kk = 0; kk < BK; kk += 8) {
                wmma::fragment<wmma::matrix_a, 16, 16, 8, wmma::precision::tf32,
                               wmma::row_major> af, afl;
                wmma::load_matrix_sync(af, &sA[cur][m0 * LDA + kk], LDA);
#pragma unroll
                for (int t = 0; t < af.num_elements; t++) {
                    const float hi = wmma::__float_to_tf32(af.x[t]);
                    afl.x[t] = af.x[t] - hi;
                    af.x[t]  = hi;
                }
#pragma unroll
                for (int j = 0; j < 4; j++) {
                    wmma::fragment<wmma::matrix_b, 16, 16, 8, wmma::precision::tf32,
                                   wmma::row_major> bf, bfl;
                    wmma::load_matrix_sync(bf, &sB[cur][kk * LDB + n0 + j * 16], LDB);
#pragma unroll
                    for (int t = 0; t < bf.num_elements; t++) {
                        const float hi = wmma::__float_to_tf32(bf.x[t]);
                        bfl.x[t] = bf.x[t] - hi;
                        bf.x[t]  = hi;
                    }
                    wmma::mma_sync(acc[j], af,  bfl, acc[j]);
                    wmma::mma_sync(acc[j], afl, bf,  acc[j]);
                    wmma::mma_sync(acc[j], af,  bf,  acc[j]);
                }
            }
            __syncthreads();
        }
    }

    float* dst = g_h1p + (size_t)kz * (BATCH * 2 * D1);
#pragma unroll
    for (int j = 0; j < 4; j++)
        wmma::store_matrix_sync(
            dst + (size_t)(row0 + m0) * (2 * D1) + half * D1 + n0 + j * 16,
            acc[j], 2 * D1, wmma::mem_row_major);
}

// ---------------------------------------------------------------------------
// Kernel D2: out = (sum_kz h1p + bias) @ Wfc + bfc.
// 8 rows/block, 256 threads, Wfc staged in smem.
// ---------------------------------------------------------------------------
#define CRPB 8
__global__ __launch_bounds__(256)
void clf_kernel(const float* __restrict__ b1s,
                const float* __restrict__ b1n,
                const float* __restrict__ Wfc,
                const float* __restrict__ bfc,
                float* __restrict__ out) {
    __shared__ float sW[2 * D1 * NCLS];     // 42 KB
    __shared__ float sH[CRPB * 2 * D1];     // 8 KB
    const int row0 = blockIdx.x * CRPB;
    const int tid  = threadIdx.x;           // 256

    for (int i = tid; i < 2 * D1 * NCLS / 4; i += 256)
        reinterpret_cast<float4*>(sW)[i] =
            reinterpret_cast<const float4*>(Wfc)[i];
    for (int i = tid; i < CRPB * 2 * D1; i += 256) {
        const int c = i & 255;
        const float b = (c < D1) ? b1s[c] : b1n[c - D1];
        const size_t off = (size_t)row0 * 2 * D1 + i;
        float s = b;
#pragma unroll
        for (int kz = 0; kz < 8; kz++)
            s += g_h1p[(size_t)kz * (BATCH * 2 * D1) + off];
        sH[i] = s;
    }
    __syncthreads();

    const int warp = tid >> 5;
    const int lane = tid & 31;
    for (int pc = warp; pc < CRPB * NCLS; pc += 8) {
        const int r = pc / NCLS;
        const int c = pc % NCLS;
        float s = 0.f;
#pragma unroll
        for (int k = lane; k < 2 * D1; k += 32)
            s = fmaf(sH[r * 2 * D1 + k], sW[k * NCLS + c], s);
#pragma unroll
        for (int off = 16; off > 0; off >>= 1)
            s += __shfl_xor_sync(0xFFFFFFFFu, s, off);
        if (lane == 0) out[(row0 + r) * NCLS + c] = s + bfc[c];
    }
}

// ---------------------------------------------------------------------------
extern "C" void kernel_launch(void* const* d_in, const int* in_sizes, int n_in,
                              void* d_out, int out_size) {
    const float* features = (const float*)d_in[0];
    const int*   ids0     = (const int*)  d_in[1];
    const int*   ids1     = (const int*)  d_in[2];
    const int*   ids2     = (const int*)  d_in[3];
    const float* W2s      = (const float*)d_in[4];
    const float* b2s      = (const float*)d_in[5];
    const float* W2n      = (const float*)d_in[6];
    const float* b2n      = (const float*)d_in[7];
    const float* W1s      = (const float*)d_in[8];
    const float* b1s      = (const float*)d_in[9];
    const float* W1n      = (const float*)d_in[10];
    const float* b1n      = (const float*)d_in[11];
    const float* Wfc      = (const float*)d_in[12];
    const float* bfc      = (const float*)d_in[13];
    float* out = (float*)d_out;

    // Allow >48KB dynamic smem for the 4-stage gemm2 pipeline.
    // (Attribute set is idempotent, host-side, and not a stream-captured op.)
    cudaFuncSetAttribute(gemm2_kernel,
                         cudaFuncAttributeMaxDynamicSharedMemorySize,
                         G_SMEM_BYTES);

    agg2_kernel<<<ROWS1, 128>>>(features, ids2);
    gemm2_kernel<<<dim3(ROWS1 / BM2, 2), 256, G_SMEM_BYTES>>>(
        features, ids1, W2s, W2n);
    agg1_kernel<<<BATCH, 256>>>(b2s, b2n);
    head_gemm_kernel<<<dim3(BATCH / HBM, 2, 8), 256>>>(features, ids0, W1s, W1n);
    clf_kernel<<<BATCH / CRPB, 256>>>(b1s, b1n, Wfc, bfc, out);
}

// round 12
// speedup vs baseline: 1.3915x; 1.0053x over previous
#include <cuda_runtime.h>
#include <mma.h>

using namespace nvcuda;

// Problem constants
#define IN_DIM 512
#define BATCH  1024
#define NN1    25
#define NN2    10
#define D1     128
#define D2     128
#define NCLS   41
#define ROWS1  (BATCH * NN1)        // 25600

// Scratch (device globals; no cudaMalloc allowed)
__device__ float g_agg2[ROWS1 * IN_DIM];        // 52.4 MB
__device__ float g_agg1[BATCH * 2 * D2];        // 1 MB (atomic-accumulated)
__device__ float g_h1p [8 * BATCH * 2 * D1];    // 8 MB (split-K partials)

__device__ __forceinline__ void cp16(void* smem_dst, const void* gmem_src) {
    unsigned s = (unsigned)__cvta_generic_to_shared(smem_dst);
    asm volatile("cp.async.cg.shared.global [%0], [%1], 16;\n"
                 :: "r"(s), "l"(gmem_src));
}

// ---------------------------------------------------------------------------
// Kernel A: agg2[i,d] = mean_k flat[i*5120 + d*10 + k], flat = gathered f2 rows
// cp.async gather. Blocks g<2048 also zero g_agg1 (consumed atomically by
// gemm2's fused agg1 epilogue; stream order guarantees completion first).
// ---------------------------------------------------------------------------
__global__ void agg2_kernel(const float* __restrict__ features,
                            const int* __restrict__ ids2) {
    __shared__ __align__(16) float sbuf[NN2 * IN_DIM];
    __shared__ int sIds[NN2];
    const int g   = blockIdx.x;
    const int tid = threadIdx.x;

    if (g < 2048 && tid < 32)   // 2048 * 128 = 262144 floats
        reinterpret_cast<float4*>(g_agg1 + g * 128)[tid] =
            make_float4(0.f, 0.f, 0.f, 0.f);

    if (tid < NN2) sIds[tid] = ids2[g * NN2 + tid];
    __syncthreads();

#pragma unroll
    for (int j = 0; j < 10; j++) {
        const int i  = tid + j * 128;          // 1280 float4 total
        const int r  = i >> 7;
        const int c4 = i & 127;
        cp16(&sbuf[i * 4],
             reinterpret_cast<const float4*>(
                 features + (size_t)sIds[r] * IN_DIM) + c4);
    }
    asm volatile("cp.async.commit_group;\n");
    asm volatile("cp.async.wait_group 0;\n");
    __syncthreads();

    float* outRow = g_agg2 + (size_t)g * IN_DIM;
#pragma unroll
    for (int j = 0; j < 4; j++) {
        const int d = tid + j * 128;
        const float* p = sbuf + d * NN2;
        float s = 0.f;
#pragma unroll
        for (int k = 0; k < NN2; k++) s += p[k];
        outRow[d] = s * (1.0f / NN2);
    }
}

// ---------------------------------------------------------------------------
// Kernel B: h2 = A @ W with FUSED agg1 epilogue (h2 never hits DRAM).
// BM=128, BN=128, BK=16, 4-stage cp.async in dynamic smem (73 KB).
// blockIdx.y = half (0: features[ids1]/W2s/b2s, 1: g_agg2/W2n/b2n).
// Epilogue: acc tile -> smem, then per flat-group g (25 consecutive h2.flat
// slots = <=2 rows x consecutive cols): sum relu(val+bias) for slots in this
// block/half, atomicAdd partial/25 into g_agg1[g].
// ---------------------------------------------------------------------------
#define BM2 128
#define BK  16
#define LDA 20
#define LDB 132
#define LDC 132
#define GSTG 4
#define G_A_STG (BM2 * LDA)                     // 2560 floats
#define G_B_STG (BK * LDB)                      // 2112 floats
#define G_SMEM_FLOATS (GSTG * (G_A_STG + G_B_STG))
#define G_SMEM_BYTES  (G_SMEM_FLOATS * 4)       // 74752 B (>= tile 128*132*4)

__global__ __launch_bounds__(256, 2)
void gemm2_kernel(const float* __restrict__ features,
                  const int* __restrict__ ids1,
                  const float* __restrict__ W2s,
                  const float* __restrict__ W2n,
                  const float* __restrict__ b2s,
                  const float* __restrict__ b2n) {
    extern __shared__ __align__(16) float dsm[];
    float* sA = dsm;                       // [GSTG][BM2*LDA]
    float* sB = dsm + GSTG * G_A_STG;      // [GSTG][BK*LDB]
    __shared__ int   sIds[BM2];
    __shared__ float sbias[D2];

    const int tid  = threadIdx.x;
    const int half = blockIdx.y;
    const int row0 = blockIdx.x * BM2;
    const float* __restrict__ W = half ? W2n : W2s;
    const int nt = IN_DIM / BK;            // 32

    if (half == 0 && tid < BM2) sIds[tid] = ids1[row0 + tid];
    if (tid < D2) sbias[tid] = half ? b2n[tid] : b2s[tid];
    __syncthreads();

    auto loadTiles = [&](int kt, int buf) {
        float* a = sA + buf * G_A_STG;
        float* b = sB + buf * G_B_STG;
#pragma unroll
        for (int u = 0; u < 2; u++) {      // A: 128x16 = 512 f4
            const int i  = tid + u * 256;
            const int r  = i >> 2;
            const int c4 = i & 3;
            const float* src = half
                ? g_agg2  + (size_t)(row0 + r) * IN_DIM + kt * BK + c4 * 4
                : features + (size_t)sIds[r] * IN_DIM + kt * BK + c4 * 4;
            cp16(&a[r * LDA + c4 * 4], src);
        }
#pragma unroll
        for (int u = 0; u < 2; u++) {      // B: 16x128 = 512 f4
            const int i  = tid + u * 256;
            const int r  = i >> 5;
            const int c4 = i & 31;
            cp16(&b[r * LDB + c4 * 4],
                 W + (size_t)(kt * BK + r) * 128 + c4 * 4);
        }
        asm volatile("cp.async.commit_group;\n");
    };

    wmma::fragment<wmma::accumulator, 16, 16, 8, float> acc[2][4];
#pragma unroll
    for (int i = 0; i < 2; i++)
#pragma unroll
        for (int j = 0; j < 4; j++) wmma::fill_fragment(acc[i][j], 0.0f);

    const int warp = tid >> 5;
    const int m0 = (warp >> 1) * 32;   // 0,32,64,96
    const int n0 = (warp & 1) * 64;    // 0,64

    loadTiles(0, 0);
    loadTiles(1, 1);
    loadTiles(2, 2);

    for (int kt = 0; kt < nt; kt++) {
        if (kt + 3 < nt) {
            loadTiles(kt + 3, (kt + 3) & 3);
            asm volatile("cp.async.wait_group 3;\n");
        } else if (kt + 3 == nt) {
            asm volatile("cp.async.wait_group 2;\n");
        } else if (kt + 2 == nt) {
            asm volatile("cp.async.wait_group 1;\n");
        } else {
            asm volatile("cp.async.wait_group 0;\n");
        }
        __syncthreads();

        const int cur = kt & 3;
        const float* a = sA + cur * G_A_STG;
        const float* b = sB + cur * G_B_STG;
#pragma unroll
        for (int kk = 0; kk < BK; kk += 8) {
            wmma::fragment<wmma::matrix_a, 16, 16, 8, wmma::precision::tf32,
                           wmma::row_major> af[2];
            wmma::fragment<wmma::matrix_b, 16, 16, 8, wmma::precision::tf32,
                           wmma::row_major> bf;
#pragma unroll
            for (int i = 0; i < 2; i++)
                wmma::load_matrix_sync(af[i], &a[(m0 + i * 16) * LDA + kk], LDA);
#pragma unroll
            for (int j = 0; j < 4; j++) {
                wmma::load_matrix_sync(bf, &b[kk * LDB + n0 + j * 16], LDB);
                wmma::mma_sync(acc[0][j], af[0], bf, acc[0][j]);
                wmma::mma_sync(acc[1][j], af[1], bf, acc[1][j]);
            }
        }
        __syncthreads();
    }

    // ---- Fused agg1 epilogue (h2 tile stays in smem) ----
    // Reuse pipeline smem as 128 x LDC fp32 tile.
#pragma unroll
    for (int i = 0; i < 2; i++)
#pragma unroll
        for (int j = 0; j < 4; j++)
            wmma::store_matrix_sync(
                dsm + (size_t)(m0 + i * 16) * LDC + n0 + j * 16,
                acc[i][j], LDC, wmma::mem_row_major);
    __syncthreads();

    // Flat groups overlapping this block: q in [row0*256, (row0+128)*256).
    const int q0 = row0 * 256;
    const int g0 = q0 / NN1;
    const int g1 = (q0 + BM2 * 256 - 1) / NN1;
    for (int g = g0 + tid; g <= g1; g += 256) {
        float s = 0.f;
        int   cnt = 0;
        const int qs = g * NN1;
#pragma unroll
        for (int j = 0; j < NN1; j++) {
            const int q = qs + j;
            const int i = (q >> 8) - row0;         // h2 row rel. to block
            const int d = q & 255;                 // h2 col
            if ((unsigned)i < (unsigned)BM2 && (d >> 7) == half) {
                s += fmaxf(dsm[(size_t)i * LDC + (d & 127)] + sbias[d & 127], 0.f);
                cnt++;
            }
        }
        if (cnt) atomicAdd(&g_agg1[g], s * (1.0f / NN1));
    }
}

// ---------------------------------------------------------------------------
// Kernel D1: split-K head GEMM, 3xTF32 precision recovery.
// grid (16, 2, 8): blockIdx.y = half, blockIdx.z = kz (K-chunk of 64).
//   half 0: A = features[ids0] (K=512, kz 0..7), W = W1s
//   half 1: A = g_agg1 (K=256, kz 0..3; kz 4..7 store zeros), W = W1n
// ---------------------------------------------------------------------------
#define HBM 64
#define KCH 64

__global__ __launch_bounds__(256, 3)
void head_gemm_kernel(const float* __restrict__ features,
                      const int* __restrict__ ids0,
                      const float* __restrict__ W1s,
                      const float* __restrict__ W1n) {
    __shared__ float sA[2][HBM * LDA];   // 10.2 KB
    __shared__ float sB[2][BK * LDB];    // 16.9 KB
    __shared__ int   sIds[HBM];

    const int tid  = threadIdx.x;
    const int half = blockIdx.y;
    const int kz   = blockIdx.z;
    const int row0 = blockIdx.x * HBM;
    const int kb   = kz * KCH;
    const bool active = (half == 0) || (kz < 4);
    const float* __restrict__ W = half ? W1n : W1s;
    const int strideA = half ? 2 * D2 : IN_DIM;

    if (half == 0 && tid < HBM) sIds[tid] = ids0[row0 + tid];
    __syncthreads();

    auto loadTiles = [&](int kt, int buf) {
        {   // A: 64x16 = 256 f4
            const int r  = tid >> 2;
            const int c4 = tid & 3;
            const float* src = half
                ? g_agg1  + (size_t)(row0 + r) * strideA + kb + kt * BK + c4 * 4
                : features + (size_t)sIds[r] * strideA + kb + kt * BK + c4 * 4;
            cp16(&sA[buf][r * LDA + c4 * 4], src);
        }
#pragma unroll
        for (int u = 0; u < 2; u++) {   // B: 16x128 = 512 f4
            const int i  = tid + u * 256;
            const int r  = i >> 5;
            const int c4 = i & 31;
            cp16(&sB[buf][r * LDB + c4 * 4],
                 W + (size_t)(kb + kt * BK + r) * 128 + c4 * 4);
        }
        asm volatile("cp.async.commit_group;\n");
    };

    wmma::fragment<wmma::accumulator, 16, 16, 8, float> acc[4];
#pragma unroll
    for (int j = 0; j < 4; j++) wmma::fill_fragment(acc[j], 0.0f);

    const int warp = tid >> 5;
    const int m0 = (warp >> 1) * 16;
    const int n0 = (warp & 1) * 64;

    if (active) {
        const int nt = KCH / BK;   // 4
        loadTiles(0, 0);
        for (int kt = 0; kt < nt; kt++) {
            if (kt + 1 < nt) {
                loadTiles(kt + 1, (kt + 1) & 1);
                asm volatile("cp.async.wait_group 1;\n");
            } else {
                asm volatile("cp.async.wait_group 0;\n");
            }
            __syncthreads();

            const int cur = kt & 1;
#pragma unroll
            for (int kk = 0; kk < BK; kk += 8) {
                wmma::fragment<wmma::matrix_a, 16, 16, 8, wmma::precision::tf32,
                               wmma::row_major> af, afl;
                wmma::load_matrix_sync(af, &sA[cur][m0 * LDA + kk], LDA);
#pragma unroll
                for (int t = 0; t < af.num_elements; t++) {
                    const float hi = wmma::__float_to_tf32(af.x[t]);
                    afl.x[t] = af.x[t] - hi;
                    af.x[t]  = hi;
                }
#pragma unroll
                for (int j = 0; j < 4; j++) {
                    wmma::fragment<wmma::matrix_b, 16, 16, 8, wmma::precision::tf32,
                                   wmma::row_major> bf, bfl;
                    wmma::load_matrix_sync(bf, &sB[cur][kk * LDB + n0 + j * 16], LDB);
#pragma unroll
                    for (int t = 0; t < bf.num_elements; t++) {
                        const float hi = wmma::__float_to_tf32(bf.x[t]);
                        bfl.x[t] = bf.x[t] - hi;
                        bf.x[t]  = hi;
                    }
                    wmma::mma_sync(acc[j], af,  bfl, acc[j]);
                    wmma::mma_sync(acc[j], afl, bf,  acc[j]);
                    wmma::mma_sync(acc[j], af,  bf,  acc[j]);
                }
            }
            __syncthreads();
        }
    }

    float* dst = g_h1p + (size_t)kz * (BATCH * 2 * D1);
#pragma unroll
    for (int j = 0; j < 4; j++)
        wmma::store_matrix_sync(
            dst + (size_t)(row0 + m0) * (2 * D1) + half * D1 + n0 + j * 16,
            acc[j], 2 * D1, wmma::mem_row_major);
}

// ---------------------------------------------------------------------------
// Kernel D2: out = (sum_kz h1p + bias) @ Wfc + bfc.
// ---------------------------------------------------------------------------
#define CRPB 8
__global__ __launch_bounds__(256)
void clf_kernel(const float* __restrict__ b1s,
                const float* __restrict__ b1n,
                const float* __restrict__ Wfc,
                const float* __restrict__ bfc,
                float* __restrict__ out) {
    __shared__ float sW[2 * D1 * NCLS];     // 42 KB
    __shared__ float sH[CRPB * 2 * D1];     // 8 KB
    const int row0 = blockIdx.x * CRPB;
    const int tid  = threadIdx.x;           // 256

    for (int i = tid; i < 2 * D1 * NCLS / 4; i += 256)
        reinterpret_cast<float4*>(sW)[i] =
            reinterpret_cast<const float4*>(Wfc)[i];
    for (int i = tid; i < CRPB * 2 * D1; i += 256) {
        const int c = i & 255;
        const float b = (c < D1) ? b1s[c] : b1n[c - D1];
        const size_t off = (size_t)row0 * 2 * D1 + i;
        float s = b;
#pragma unroll
        for (int kz = 0; kz < 8; kz++)
            s += g_h1p[(size_t)kz * (BATCH * 2 * D1) + off];
        sH[i] = s;
    }
    __syncthreads();

    const int warp = tid >> 5;
    const int lane = tid & 31;
    for (int pc = warp; pc < CRPB * NCLS; pc += 8) {
        const int r = pc / NCLS;
        const int c = pc % NCLS;
        float s = 0.f;
#pragma unroll
        for (int k = lane; k < 2 * D1; k += 32)
            s = fmaf(sH[r * 2 * D1 + k], sW[k * NCLS + c], s);
#pragma unroll
        for (int off = 16; off > 0; off >>= 1)
            s += __shfl_xor_sync(0xFFFFFFFFu, s, off);
        if (lane == 0) out[(row0 + r) * NCLS + c] = s + bfc[c];
    }
}

// ---------------------------------------------------------------------------
extern "C" void kernel_launch(void* const* d_in, const int* in_sizes, int n_in,
                              void* d_out, int out_size) {
    const float* features = (const float*)d_in[0];
    const int*   ids0     = (const int*)  d_in[1];
    const int*   ids1     = (const int*)  d_in[2];
    const int*   ids2     = (const int*)  d_in[3];
    const float* W2s      = (const float*)d_in[4];
    const float* b2s      = (const float*)d_in[5];
    const float* W2n      = (const float*)d_in[6];
    const float* b2n      = (const float*)d_in[7];
    const float* W1s      = (const float*)d_in[8];
    const float* b1s      = (const float*)d_in[9];
    const float* W1n      = (const float*)d_in[10];
    const float* b1n      = (const float*)d_in[11];
    const float* Wfc      = (const float*)d_in[12];
    const float* bfc      = (const float*)d_in[13];
    float* out = (float*)d_out;

    cudaFuncSetAttribute(gemm2_kernel,
                         cudaFuncAttributeMaxDynamicSharedMemorySize,
                         G_SMEM_BYTES);

    agg2_kernel<<<ROWS1, 128>>>(features, ids2);
    gemm2_kernel<<<dim3(ROWS1 / BM2, 2), 256, G_SMEM_BYTES>>>(
        features, ids1, W2s, W2n, b2s, b2n);
    head_gemm_kernel<<<dim3(BATCH / HBM, 2, 8), 256>>>(features, ids0, W1s, W1n);
    clf_kernel<<<BATCH / CRPB, 256>>>(b1s, b1n, Wfc, bfc, out);
}

// round 14
// speedup vs baseline: 1.4208x; 1.0211x over previous
#include <cuda_runtime.h>
#include <mma.h>

using namespace nvcuda;

// Problem constants
#define IN_DIM 512
#define BATCH  1024
#define NN1    25
#define NN2    10
#define D1     128
#define D2     128
#define NCLS   41
#define ROWS1  (BATCH * NN1)        // 25600

// Scratch (device globals; no cudaMalloc allowed)
__device__ float g_agg2[ROWS1 * IN_DIM];        // 52.4 MB
__device__ float g_agg1[BATCH * 2 * D2];        // 1 MB (atomic-accumulated)
__device__ float g_h1  [BATCH * 2 * D1];        // 1 MB (atomic-accumulated)

__device__ __forceinline__ void cp16(void* smem_dst, const void* gmem_src) {
    unsigned s = (unsigned)__cvta_generic_to_shared(smem_dst);
    asm volatile("cp.async.cg.shared.global [%0], [%1], 16;\n"
                 :: "r"(s), "l"(gmem_src));
}

// ---------------------------------------------------------------------------
// Kernel A: agg2[i,d] = mean_k flat[i*5120 + d*10 + k], flat = gathered f2 rows
// cp.async gather. Blocks g<2048 also zero g_agg1 and g_h1 (both consumed
// atomically downstream; stream order guarantees completion first).
// ---------------------------------------------------------------------------
__global__ void agg2_kernel(const float* __restrict__ features,
                            const int* __restrict__ ids2) {
    __shared__ __align__(16) float sbuf[NN2 * IN_DIM];
    __shared__ int sIds[NN2];
    const int g   = blockIdx.x;
    const int tid = threadIdx.x;

    if (g < 2048 && tid < 32) {  // 2048 * 128 = 262144 floats each
        reinterpret_cast<float4*>(g_agg1 + g * 128)[tid] =
            make_float4(0.f, 0.f, 0.f, 0.f);
        reinterpret_cast<float4*>(g_h1 + g * 128)[tid] =
            make_float4(0.f, 0.f, 0.f, 0.f);
    }

    if (tid < NN2) sIds[tid] = ids2[g * NN2 + tid];
    __syncthreads();

#pragma unroll
    for (int j = 0; j < 10; j++) {
        const int i  = tid + j * 128;          // 1280 float4 total
        const int r  = i >> 7;
        const int c4 = i & 127;
        cp16(&sbuf[i * 4],
             reinterpret_cast<const float4*>(
                 features + (size_t)sIds[r] * IN_DIM) + c4);
    }
    asm volatile("cp.async.commit_group;\n");
    asm volatile("cp.async.wait_group 0;\n");
    __syncthreads();

    float* outRow = g_agg2 + (size_t)g * IN_DIM;
#pragma unroll
    for (int j = 0; j < 4; j++) {
        const int d = tid + j * 128;
        const float* p = sbuf + d * NN2;
        float s = 0.f;
#pragma unroll
        for (int k = 0; k < NN2; k++) s += p[k];
        outRow[d] = s * (1.0f / NN2);
    }
}

// ---------------------------------------------------------------------------
// Kernel B: h2 = A @ W with FUSED agg1 epilogue (h2 never hits DRAM).
// BM=128, BN=128, BK=16, 4-stage cp.async in dynamic smem (73 KB).
// blockIdx.y = half (0: features[ids1]/W2s/b2s, 1: g_agg2/W2n/b2n).
// ---------------------------------------------------------------------------
#define BM2 128
#define BK  16
#define LDA 20
#define LDB 132
#define LDC 132
#define GSTG 4
#define G_A_STG (BM2 * LDA)                     // 2560 floats
#define G_B_STG (BK * LDB)                      // 2112 floats
#define G_SMEM_FLOATS (GSTG * (G_A_STG + G_B_STG))
#define G_SMEM_BYTES  (G_SMEM_FLOATS * 4)       // 74752 B (>= tile 128*132*4)

__global__ __launch_bounds__(256, 2)
void gemm2_kernel(const float* __restrict__ features,
                  const int* __restrict__ ids1,
                  const float* __restrict__ W2s,
                  const float* __restrict__ W2n,
                  const float* __restrict__ b2s,
                  const float* __restrict__ b2n) {
    extern __shared__ __align__(16) float dsm[];
    float* sA = dsm;                       // [GSTG][BM2*LDA]
    float* sB = dsm + GSTG * G_A_STG;      // [GSTG][BK*LDB]
    __shared__ int   sIds[BM2];
    __shared__ float sbias[D2];

    const int tid  = threadIdx.x;
    const int half = blockIdx.y;
    const int row0 = blockIdx.x * BM2;
    const float* __restrict__ W = half ? W2n : W2s;
    const int nt = IN_DIM / BK;            // 32

    if (half == 0 && tid < BM2) sIds[tid] = ids1[row0 + tid];
    if (tid < D2) sbias[tid] = half ? b2n[tid] : b2s[tid];
    __syncthreads();

    auto loadTiles = [&](int kt, int buf) {
        float* a = sA + buf * G_A_STG;
        float* b = sB + buf * G_B_STG;
#pragma unroll
        for (int u = 0; u < 2; u++) {      // A: 128x16 = 512 f4
            const int i  = tid + u * 256;
            const int r  = i >> 2;
            const int c4 = i & 3;
            const float* src = half
                ? g_agg2  + (size_t)(row0 + r) * IN_DIM + kt * BK + c4 * 4
                : features + (size_t)sIds[r] * IN_DIM + kt * BK + c4 * 4;
            cp16(&a[r * LDA + c4 * 4], src);
        }
#pragma unroll
        for (int u = 0; u < 2; u++) {      // B: 16x128 = 512 f4
            const int i  = tid + u * 256;
            const int r  = i >> 5;
            const int c4 = i & 31;
            cp16(&b[r * LDB + c4 * 4],
                 W + (size_t)(kt * BK + r) * 128 + c4 * 4);
        }
        asm volatile("cp.async.commit_group;\n");
    };

    wmma::fragment<wmma::accumulator, 16, 16, 8, float> acc[2][4];
#pragma unroll
    for (int i = 0; i < 2; i++)
#pragma unroll
        for (int j = 0; j < 4; j++) wmma::fill_fragment(acc[i][j], 0.0f);

    const int warp = tid >> 5;
    const int m0 = (warp >> 1) * 32;   // 0,32,64,96
    const int n0 = (warp & 1) * 64;    // 0,64

    loadTiles(0, 0);
    loadTiles(1, 1);
    loadTiles(2, 2);

    for (int kt = 0; kt < nt; kt++) {
        if (kt + 3 < nt) {
            loadTiles(kt + 3, (kt + 3) & 3);
            asm volatile("cp.async.wait_group 3;\n");
        } else if (kt + 3 == nt) {
            asm volatile("cp.async.wait_group 2;\n");
        } else if (kt + 2 == nt) {
            asm volatile("cp.async.wait_group 1;\n");
        } else {
            asm volatile("cp.async.wait_group 0;\n");
        }
        __syncthreads();

        const int cur = kt & 3;
        const float* a = sA + cur * G_A_STG;
        const float* b = sB + cur * G_B_STG;
#pragma unroll
        for (int kk = 0; kk < BK; kk += 8) {
            wmma::fragment<wmma::matrix_a, 16, 16, 8, wmma::precision::tf32,
                           wmma::row_major> af[2];
            wmma::fragment<wmma::matrix_b, 16, 16, 8, wmma::precision::tf32,
                           wmma::row_major> bf;
#pragma unroll
            for (int i = 0; i < 2; i++)
                wmma::load_matrix_sync(af[i], &a[(m0 + i * 16) * LDA + kk], LDA);
#pragma unroll
            for (int j = 0; j < 4; j++) {
                wmma::load_matrix_sync(bf, &b[kk * LDB + n0 + j * 16], LDB);
                wmma::mma_sync(acc[0][j], af[0], bf, acc[0][j]);
                wmma::mma_sync(acc[1][j], af[1], bf, acc[1][j]);
            }
        }
        __syncthreads();
    }

    // ---- Fused agg1 epilogue (h2 tile stays in smem) ----
#pragma unroll
    for (int i = 0; i < 2; i++)
#pragma unroll
        for (int j = 0; j < 4; j++)
            wmma::store_matrix_sync(
                dsm + (size_t)(m0 + i * 16) * LDC + n0 + j * 16,
                acc[i][j], LDC, wmma::mem_row_major);
    __syncthreads();

    const int q0 = row0 * 256;
    const int g0 = q0 / NN1;
    const int g1 = (q0 + BM2 * 256 - 1) / NN1;
    for (int g = g0 + tid; g <= g1; g += 256) {
        float s = 0.f;
        int   cnt = 0;
        const int qs = g * NN1;
#pragma unroll
        for (int j = 0; j < NN1; j++) {
            const int q = qs + j;
            const int i = (q >> 8) - row0;
            const int d = q & 255;
            if ((unsigned)i < (unsigned)BM2 && (d >> 7) == half) {
                s += fmaxf(dsm[(size_t)i * LDC + (d & 127)] + sbias[d & 127], 0.f);
                cnt++;
            }
        }
        if (cnt) atomicAdd(&g_agg1[g], s * (1.0f / NN1));
    }
}

// ---------------------------------------------------------------------------
// Kernel D1: split-K head GEMM, 3xTF32, partials ATOMICALLY accumulated
// into g_h1 (zeroed by agg2). grid (16, 2, 4): y = half, z = kz (K=128).
//   half 0: A = features[ids0] (K=512, kz 0..3), W = W1s
//   half 1: A = g_agg1 (K=256, kz 0..1; kz 2..3 exit), W = W1n
// ---------------------------------------------------------------------------
#define HBM 64
#define KCH 128

__global__ __launch_bounds__(256, 3)
void head_gemm_kernel(const float* __restrict__ features,
                      const int* __restrict__ ids0,
                      const float* __restrict__ W1s,
                      const float* __restrict__ W1n) {
    // Pool reused: pipeline (2*HBM*LDA + 2*BK*LDB = 6784 floats) then as
    // 64x128 output tile (8192 floats).
    __shared__ __align__(16) float pool[HBM * 128];   // 32.8 KB
    __shared__ int sIds[HBM];
    float* sA = pool;                          // [2][HBM*LDA] = 2560
    float* sB = pool + 2 * HBM * LDA;          // [2][BK*LDB]  = 4224

    const int tid  = threadIdx.x;
    const int half = blockIdx.y;
    const int kz   = blockIdx.z;
    if (half == 1 && kz >= 2) return;
    const int row0 = blockIdx.x * HBM;
    const int kb   = kz * KCH;
    const float* __restrict__ W = half ? W1n : W1s;
    const int strideA = half ? 2 * D2 : IN_DIM;

    if (half == 0 && tid < HBM) sIds[tid] = ids0[row0 + tid];
    __syncthreads();

    auto loadTiles = [&](int kt, int buf) {
        float* a = sA + buf * (HBM * LDA);
        float* b = sB + buf * (BK * LDB);
        {   // A: 64x16 = 256 f4
            const int r  = tid >> 2;
            const int c4 = tid & 3;
            const float* src = half
                ? g_agg1  + (size_t)(row0 + r) * strideA + kb + kt * BK + c4 * 4
                : features + (size_t)sIds[r] * strideA + kb + kt * BK + c4 * 4;
            cp16(&a[r * LDA + c4 * 4], src);
        }
#pragma unroll
        for (int u = 0; u < 2; u++) {   // B: 16x128 = 512 f4
            const int i  = tid + u * 256;
            const int r  = i >> 5;
            const int c4 = i & 31;
            cp16(&b[r * LDB + c4 * 4],
                 W + (size_t)(kb + kt * BK + r) * 128 + c4 * 4);
        }
        asm volatile("cp.async.commit_group;\n");
    };

    wmma::fragment<wmma::accumulator, 16, 16, 8, float> acc[4];
#pragma unroll
    for (int j = 0; j < 4; j++) wmma::fill_fragment(acc[j], 0.0f);

    const int warp = tid >> 5;
    const int m0 = (warp >> 1) * 16;
    const int n0 = (warp & 1) * 64;

    const int nt = KCH / BK;   // 8
    loadTiles(0, 0);
    for (int kt = 0; kt < nt; kt++) {
        if (kt + 1 < nt) {
            loadTiles(kt + 1, (kt + 1) & 1);
            asm volatile("cp.async.wait_group 1;\n");
        } else {
            asm volatile("cp.async.wait_group 0;\n");
        }
        __syncthreads();

        const int cur = kt & 1;
        const float* a = sA + cur * (HBM * LDA);
        const float* b = sB + cur * (BK * LDB);
#pragma unroll
        for (int kk = 0; kk < BK; kk += 8) {
            wmma::fragment<wmma::matrix_a, 16, 16, 8, wmma::precision::tf32,
                           wmma::row_major> af, afl;
            wmma::load_matrix_sync(af, &a[m0 * LDA + kk], LDA);
#pragma unroll
            for (int t = 0; t < af.num_elements; t++) {
                const float hi = wmma::__float_to_tf32(af.x[t]);
                afl.x[t] = af.x[t] - hi;
                af.x[t]  = hi;
            }
#pragma unroll
            for (int j = 0; j < 4; j++) {
                wmma::fragment<wmma::matrix_b, 16, 16, 8, wmma::precision::tf32,
                               wmma::row_major> bf, bfl;
                wmma::load_matrix_sync(bf, &b[kk * LDB + n0 + j * 16], LDB);
#pragma unroll
                for (int t = 0; t < bf.num_elements; t++) {
                    const float hi = wmma::__float_to_tf32(bf.x[t]);
                    bfl.x[t] = bf.x[t] - hi;
                    bf.x[t]  = hi;
                }
                wmma::mma_sync(acc[j], af,  bfl, acc[j]);
                wmma::mma_sync(acc[j], afl, bf,  acc[j]);
                wmma::mma_sync(acc[j], af,  bf,  acc[j]);
            }
        }
        __syncthreads();
    }

    // Dump accumulators to the pool (now free) and atomically fold into g_h1.
#pragma unroll
    for (int j = 0; j < 4; j++)
        wmma::store_matrix_sync(pool + (size_t)m0 * 128 + n0 + j * 16,
                                acc[j], 128, wmma::mem_row_major);
    __syncthreads();

#pragma unroll
    for (int u = 0; u < HBM * 128 / 256; u++) {    // 32 elems/thread
        const int i = tid + u * 256;
        const int r = i >> 7;
        const int c = i & 127;
        atomicAdd(&g_h1[(size_t)(row0 + r) * (2 * D1) + half * D1 + c], pool[i]);
    }
}

// ---------------------------------------------------------------------------
// Kernel D2: out = (g_h1 + bias) @ Wfc + bfc. 4 rows/block, grid 256.
// ---------------------------------------------------------------------------
#define CRPB 4
__global__ __launch_bounds__(256)
void clf_kernel(const float* __restrict__ b1s,
                const float* __restrict__ b1n,
                const float* __restrict__ Wfc,
                const float* __restrict__ bfc,
                float* __restrict__ out) {
    __shared__ float sW[2 * D1 * NCLS];     // 42 KB
    __shared__ float sH[CRPB * 2 * D1];     // 4 KB
    const int row0 = blockIdx.x * CRPB;
    const int tid  = threadIdx.x;           // 256

    for (int i = tid; i < 2 * D1 * NCLS / 4; i += 256)
        reinterpret_cast<float4*>(sW)[i] =
            reinterpret_cast<const float4*>(Wfc)[i];
    for (int i = tid; i < CRPB * 2 * D1; i += 256) {
        const int c = i & 255;
        const float b = (c < D1) ? b1s[c] : b1n[c - D1];
        sH[i] = g_h1[(size_t)row0 * 2 * D1 + i] + b;
    }
    __syncthreads();

    const int warp = tid >> 5;
    const int lane = tid & 31;
    for (int pc = warp; pc < CRPB * NCLS; pc += 8) {
        const int r = pc / NCLS;
        const int c = pc % NCLS;
        float s = 0.f;
#pragma unroll
        for (int k = lane; k < 2 * D1; k += 32)
            s = fmaf(sH[r * 2 * D1 + k], sW[k * NCLS + c], s);
#pragma unroll
        for (int off = 16; off > 0; off >>= 1)
            s += __shfl_xor_sync(0xFFFFFFFFu, s, off);
        if (lane == 0) out[(row0 + r) * NCLS + c] = s + bfc[c];
    }
}

// ---------------------------------------------------------------------------
extern "C" void kernel_launch(void* const* d_in, const int* in_sizes, int n_in,
                              void* d_out, int out_size) {
    const float* features = (const float*)d_in[0];
    const int*   ids0     = (const int*)  d_in[1];
    const int*   ids1     = (const int*)  d_in[2];
    const int*   ids2     = (const int*)  d_in[3];
    const float* W2s      = (const float*)d_in[4];
    const float* b2s      = (const float*)d_in[5];
    const float* W2n      = (const float*)d_in[6];
    const float* b2n      = (const float*)d_in[7];
    const float* W1s      = (const float*)d_in[8];
    const float* b1s      = (const float*)d_in[9];
    const float* W1n      = (const float*)d_in[10];
    const float* b1n      = (const float*)d_in[11];
    const float* Wfc      = (const float*)d_in[12];
    const float* bfc      = (const float*)d_in[13];
    float* out = (float*)d_out;

    cudaFuncSetAttribute(gemm2_kernel,
                         cudaFuncAttributeMaxDynamicSharedMemorySize,
                         G_SMEM_BYTES);

    agg2_kernel<<<ROWS1, 128>>>(features, ids2);
    gemm2_kernel<<<dim3(ROWS1 / BM2, 2), 256, G_SMEM_BYTES>>>(
        features, ids1, W2s, W2n, b2s, b2n);
    head_gemm_kernel<<<dim3(BATCH / HBM, 2, 4), 256>>>(features, ids0, W1s, W1n);
    clf_kernel<<<BATCH / CRPB, 256>>>(b1s, b1n, Wfc, bfc, out);
}

// round 15
// speedup vs baseline: 1.4333x; 1.0088x over previous
#include <cuda_runtime.h>
#include <mma.h>

using namespace nvcuda;

// Problem constants
#define IN_DIM 512
#define BATCH  1024
#define NN1    25
#define NN2    10
#define D1     128
#define D2     128
#define NCLS   41
#define ROWS1  (BATCH * NN1)        // 25600

// Scratch (device globals; no cudaMalloc allowed)
__device__ float g_agg2[ROWS1 * IN_DIM];        // 52.4 MB
__device__ float g_agg1[BATCH * 2 * D2];        // 1 MB (atomic-accumulated)
__device__ float g_h1  [BATCH * 2 * D1];        // 1 MB (atomic-accumulated)

__device__ __forceinline__ void cp16(void* smem_dst, const void* gmem_src) {
    unsigned s = (unsigned)__cvta_generic_to_shared(smem_dst);
    asm volatile("cp.async.cg.shared.global [%0], [%1], 16;\n"
                 :: "r"(s), "l"(gmem_src));
}

// ---------------------------------------------------------------------------
// Kernel A: agg2[i,d] = mean_k flat[i*5120 + d*10 + k], flat = gathered f2 rows
// cp.async gather. Blocks g<2048 also zero g_agg1 and g_h1 (both consumed
// atomically downstream; stream order guarantees completion first).
// ---------------------------------------------------------------------------
__global__ void agg2_kernel(const float* __restrict__ features,
                            const int* __restrict__ ids2) {
    __shared__ __align__(16) float sbuf[NN2 * IN_DIM];
    __shared__ int sIds[NN2];
    const int g   = blockIdx.x;
    const int tid = threadIdx.x;

    if (g < 2048 && tid < 32) {  // 2048 * 128 = 262144 floats each
        reinterpret_cast<float4*>(g_agg1 + g * 128)[tid] =
            make_float4(0.f, 0.f, 0.f, 0.f);
        reinterpret_cast<float4*>(g_h1 + g * 128)[tid] =
            make_float4(0.f, 0.f, 0.f, 0.f);
    }

    if (tid < NN2) sIds[tid] = ids2[g * NN2 + tid];
    __syncthreads();

#pragma unroll
    for (int j = 0; j < 10; j++) {
        const int i  = tid + j * 128;          // 1280 float4 total
        const int r  = i >> 7;
        const int c4 = i & 127;
        cp16(&sbuf[i * 4],
             reinterpret_cast<const float4*>(
                 features + (size_t)sIds[r] * IN_DIM) + c4);
    }
    asm volatile("cp.async.commit_group;\n");
    asm volatile("cp.async.wait_group 0;\n");
    __syncthreads();

    float* outRow = g_agg2 + (size_t)g * IN_DIM;
#pragma unroll
    for (int j = 0; j < 4; j++) {
        const int d = tid + j * 128;
        const float* p = sbuf + d * NN2;
        float s = 0.f;
#pragma unroll
        for (int k = 0; k < NN2; k++) s += p[k];
        outRow[d] = s * (1.0f / NN2);
    }
}

// ---------------------------------------------------------------------------
// Kernel B: h2 = A @ W with FUSED agg1 epilogue (h2 never hits DRAM).
// BM=128, BN=128, BK=16, 4-stage cp.async in dynamic smem (73 KB).
// blockIdx.y = half (0: features[ids1]/W2s/b2s, 1: g_agg2/W2n/b2n).
// ---------------------------------------------------------------------------
#define BM2 128
#define BK  16
#define LDA 20
#define LDB 132
#define LDC 132
#define GSTG 4
#define G_A_STG (BM2 * LDA)                     // 2560 floats
#define G_B_STG (BK * LDB)                      // 2112 floats
#define G_SMEM_FLOATS (GSTG * (G_A_STG + G_B_STG))
#define G_SMEM_BYTES  (G_SMEM_FLOATS * 4)       // 74752 B (>= tile 128*132*4)

__global__ __launch_bounds__(256, 2)
void gemm2_kernel(const float* __restrict__ features,
                  const int* __restrict__ ids1,
                  const float* __restrict__ W2s,
                  const float* __restrict__ W2n,
                  const float* __restrict__ b2s,
                  const float* __restrict__ b2n) {
    extern __shared__ __align__(16) float dsm[];
    float* sA = dsm;                       // [GSTG][BM2*LDA]
    float* sB = dsm + GSTG * G_A_STG;      // [GSTG][BK*LDB]
    __shared__ int   sIds[BM2];
    __shared__ float sbias[D2];

    const int tid  = threadIdx.x;
    const int half = blockIdx.y;
    const int row0 = blockIdx.x * BM2;
    const float* __restrict__ W = half ? W2n : W2s;
    const int nt = IN_DIM / BK;            // 32

    if (half == 0 && tid < BM2) sIds[tid] = ids1[row0 + tid];
    if (tid < D2) sbias[tid] = half ? b2n[tid] : b2s[tid];
    __syncthreads();

    auto loadTiles = [&](int kt, int buf) {
        float* a = sA + buf * G_A_STG;
        float* b = sB + buf * G_B_STG;
#pragma unroll
        for (int u = 0; u < 2; u++) {      // A: 128x16 = 512 f4
            const int i  = tid + u * 256;
            const int r  = i >> 2;
            const int c4 = i & 3;
            const float* src = half
                ? g_agg2  + (size_t)(row0 + r) * IN_DIM + kt * BK + c4 * 4
                : features + (size_t)sIds[r] * IN_DIM + kt * BK + c4 * 4;
            cp16(&a[r * LDA + c4 * 4], src);
        }
#pragma unroll
        for (int u = 0; u < 2; u++) {      // B: 16x128 = 512 f4
            const int i  = tid + u * 256;
            const int r  = i >> 5;
            const int c4 = i & 31;
            cp16(&b[r * LDB + c4 * 4],
                 W + (size_t)(kt * BK + r) * 128 + c4 * 4);
        }
        asm volatile("cp.async.commit_group;\n");
    };

    wmma::fragment<wmma::accumulator, 16, 16, 8, float> acc[2][4];
#pragma unroll
    for (int i = 0; i < 2; i++)
#pragma unroll
        for (int j = 0; j < 4; j++) wmma::fill_fragment(acc[i][j], 0.0f);

    const int warp = tid >> 5;
    const int m0 = (warp >> 1) * 32;   // 0,32,64,96
    const int n0 = (warp & 1) * 64;    // 0,64

    loadTiles(0, 0);
    loadTiles(1, 1);
    loadTiles(2, 2);

    for (int kt = 0; kt < nt; kt++) {
        if (kt + 3 < nt) {
            loadTiles(kt + 3, (kt + 3) & 3);
            asm volatile("cp.async.wait_group 3;\n");
        } else if (kt + 3 == nt) {
            asm volatile("cp.async.wait_group 2;\n");
        } else if (kt + 2 == nt) {
            asm volatile("cp.async.wait_group 1;\n");
        } else {
            asm volatile("cp.async.wait_group 0;\n");
        }
        __syncthreads();

        const int cur = kt & 3;
        const float* a = sA + cur * G_A_STG;
        const float* b = sB + cur * G_B_STG;
#pragma unroll
        for (int kk = 0; kk < BK; kk += 8) {
            wmma::fragment<wmma::matrix_a, 16, 16, 8, wmma::precision::tf32,
                           wmma::row_major> af[2];
            wmma::fragment<wmma::matrix_b, 16, 16, 8, wmma::precision::tf32,
                           wmma::row_major> bf;
#pragma unroll
            for (int i = 0; i < 2; i++)
                wmma::load_matrix_sync(af[i], &a[(m0 + i * 16) * LDA + kk], LDA);
#pragma unroll
            for (int j = 0; j < 4; j++) {
                wmma::load_matrix_sync(bf, &b[kk * LDB + n0 + j * 16], LDB);
                wmma::mma_sync(acc[0][j], af[0], bf, acc[0][j]);
                wmma::mma_sync(acc[1][j], af[1], bf, acc[1][j]);
            }
        }
        __syncthreads();
    }

    // ---- Fused agg1 epilogue (h2 tile stays in smem) ----
#pragma unroll
    for (int i = 0; i < 2; i++)
#pragma unroll
        for (int j = 0; j < 4; j++)
            wmma::store_matrix_sync(
                dsm + (size_t)(m0 + i * 16) * LDC + n0 + j * 16,
                acc[i][j], LDC, wmma::mem_row_major);
    __syncthreads();

    const int q0 = row0 * 256;
    const int g0 = q0 / NN1;
    const int g1 = (q0 + BM2 * 256 - 1) / NN1;
    for (int g = g0 + tid; g <= g1; g += 256) {
        float s = 0.f;
        int   cnt = 0;
        const int qs = g * NN1;
#pragma unroll
        for (int j = 0; j < NN1; j++) {
            const int q = qs + j;
            const int i = (q >> 8) - row0;
            const int d = q & 255;
            if ((unsigned)i < (unsigned)BM2 && (d >> 7) == half) {
                s += fmaxf(dsm[(size_t)i * LDC + (d & 127)] + sbias[d & 127], 0.f);
                cnt++;
            }
        }
        if (cnt) atomicAdd(&g_agg1[g], s * (1.0f / NN1));
    }
}

// ---------------------------------------------------------------------------
// Kernel D1: split-K head GEMM, 3xTF32, partials ATOMICALLY accumulated
// into g_h1 (zeroed by agg2). grid (16, 2, 4): y = half, z = kz (K=128).
//   half 0: A = features[ids0] (K=512, kz 0..3), W = W1s
//   half 1: A = g_agg1 (K=256, kz 0..1; kz 2..3 exit), W = W1n
// ---------------------------------------------------------------------------
#define HBM 64
#define KCH 128

__global__ __launch_bounds__(256, 3)
void head_gemm_kernel(const float* __restrict__ features,
                      const int* __restrict__ ids0,
                      const float* __restrict__ W1s,
                      const float* __restrict__ W1n) {
    __shared__ __align__(16) float pool[HBM * 128];   // 32.8 KB
    __shared__ int sIds[HBM];
    float* sA = pool;                          // [2][HBM*LDA] = 2560
    float* sB = pool + 2 * HBM * LDA;          // [2][BK*LDB]  = 4224

    const int tid  = threadIdx.x;
    const int half = blockIdx.y;
    const int kz   = blockIdx.z;
    if (half == 1 && kz >= 2) return;
    const int row0 = blockIdx.x * HBM;
    const int kb   = kz * KCH;
    const float* __restrict__ W = half ? W1n : W1s;
    const int strideA = half ? 2 * D2 : IN_DIM;

    if (half == 0 && tid < HBM) sIds[tid] = ids0[row0 + tid];
    __syncthreads();

    auto loadTiles = [&](int kt, int buf) {
        float* a = sA + buf * (HBM * LDA);
        float* b = sB + buf * (BK * LDB);
        {   // A: 64x16 = 256 f4
            const int r  = tid >> 2;
            const int c4 = tid & 3;
            const float* src = half
                ? g_agg1  + (size_t)(row0 + r) * strideA + kb + kt * BK + c4 * 4
                : features + (size_t)sIds[r] * strideA + kb + kt * BK + c4 * 4;
            cp16(&a[r * LDA + c4 * 4], src);
        }
#pragma unroll
        for (int u = 0; u < 2; u++) {   // B: 16x128 = 512 f4
            const int i  = tid + u * 256;
            const int r  = i >> 5;
            const int c4 = i & 31;
            cp16(&b[r * LDB + c4 * 4],
                 W + (size_t)(kb + kt * BK + r) * 128 + c4 * 4);
        }
        asm volatile("cp.async.commit_group;\n");
    };

    wmma::fragment<wmma::accumulator, 16, 16, 8, float> acc[4];
#pragma unroll
    for (int j = 0; j < 4; j++) wmma::fill_fragment(acc[j], 0.0f);

    const int warp = tid >> 5;
    const int m0 = (warp >> 1) * 16;
    const int n0 = (warp & 1) * 64;

    const int nt = KCH / BK;   // 8
    loadTiles(0, 0);
    for (int kt = 0; kt < nt; kt++) {
        if (kt + 1 < nt) {
            loadTiles(kt + 1, (kt + 1) & 1);
            asm volatile("cp.async.wait_group 1;\n");
        } else {
            asm volatile("cp.async.wait_group 0;\n");
        }
        __syncthreads();

        const int cur = kt & 1;
        const float* a = sA + cur * (HBM * LDA);
        const float* b = sB + cur * (BK * LDB);
#pragma unroll
        for (int kk = 0; kk < BK; kk += 8) {
            wmma::fragment<wmma::matrix_a, 16, 16, 8, wmma::precision::tf32,
                           wmma::row_major> af, afl;
            wmma::load_matrix_sync(af, &a[m0 * LDA + kk], LDA);
#pragma unroll
            for (int t = 0; t < af.num_elements; t++) {
                const float hi = wmma::__float_to_tf32(af.x[t]);
                afl.x[t] = af.x[t] - hi;
                af.x[t]  = hi;
            }
#pragma unroll
            for (int j = 0; j < 4; j++) {
                wmma::fragment<wmma::matrix_b, 16, 16, 8, wmma::precision::tf32,
                               wmma::row_major> bf, bfl;
                wmma::load_matrix_sync(bf, &b[kk * LDB + n0 + j * 16], LDB);
#pragma unroll
                for (int t = 0; t < bf.num_elements; t++) {
                    const float hi = wmma::__float_to_tf32(bf.x[t]);
                    bfl.x[t] = bf.x[t] - hi;
                    bf.x[t]  = hi;
                }
                wmma::mma_sync(acc[j], af,  bfl, acc[j]);
                wmma::mma_sync(acc[j], afl, bf,  acc[j]);
                wmma::mma_sync(acc[j], af,  bf,  acc[j]);
            }
        }
        __syncthreads();
    }

    // Dump accumulators to the pool (now free) and atomically fold into g_h1.
#pragma unroll
    for (int j = 0; j < 4; j++)
        wmma::store_matrix_sync(pool + (size_t)m0 * 128 + n0 + j * 16,
                                acc[j], 128, wmma::mem_row_major);
    __syncthreads();

#pragma unroll
    for (int u = 0; u < HBM * 128 / 256; u++) {    // 32 elems/thread
        const int i = tid + u * 256;
        const int r = i >> 7;
        const int c = i & 127;
        atomicAdd(&g_h1[(size_t)(row0 + r) * (2 * D1) + half * D1 + c], pool[i]);
    }
}

// ---------------------------------------------------------------------------
// Kernel D2: out = (g_h1 + bias) @ Wfc + bfc. 4 rows/block, grid 256.
// Wfc staged TRANSPOSED in smem (row stride 257 -> bank = (c+k) mod 32,
// conflict-free). One thread per (row, class); 4 accumulators; no shfl.
// ---------------------------------------------------------------------------
#define CRPB 4
#define WSTR 257
__global__ __launch_bounds__(256)
void clf_kernel(const float* __restrict__ b1s,
                const float* __restrict__ b1n,
                const float* __restrict__ Wfc,
                const float* __restrict__ bfc,
                float* __restrict__ out) {
    __shared__ float sWt[NCLS * WSTR];      // 42.1 KB (transposed, padded)
    __shared__ float sH[CRPB * 2 * D1];     // 4 KB
    const int row0 = blockIdx.x * CRPB;
    const int tid  = threadIdx.x;           // 256

    // Stage Wfc transposed: coalesced f4 reads, scattered scalar smem writes.
    for (int i4 = tid; i4 < 2 * D1 * NCLS / 4; i4 += 256) {   // 2624
        const float4 v = reinterpret_cast<const float4*>(Wfc)[i4];
        int j = i4 * 4;
        sWt[(j % NCLS) * WSTR + (j / NCLS)] = v.x; j++;
        sWt[(j % NCLS) * WSTR + (j / NCLS)] = v.y; j++;
        sWt[(j % NCLS) * WSTR + (j / NCLS)] = v.z; j++;
        sWt[(j % NCLS) * WSTR + (j / NCLS)] = v.w;
    }
    for (int i = tid; i < CRPB * 2 * D1; i += 256) {
        const int c = i & 255;
        const float b = (c < D1) ? b1s[c] : b1n[c - D1];
        sH[i] = g_h1[(size_t)row0 * 2 * D1 + i] + b;
    }
    __syncthreads();

    if (tid < CRPB * NCLS) {               // 164 outputs
        const int r = tid / NCLS;
        const int c = tid % NCLS;
        const float* h = sH + r * 2 * D1;
        const float* w = sWt + c * WSTR;
        float a0 = 0.f, a1 = 0.f, a2 = 0.f, a3 = 0.f;
#pragma unroll 8
        for (int k = 0; k < 2 * D1; k += 4) {
            a0 = fmaf(h[k + 0], w[k + 0], a0);
            a1 = fmaf(h[k + 1], w[k + 1], a1);
            a2 = fmaf(h[k + 2], w[k + 2], a2);
            a3 = fmaf(h[k + 3], w[k + 3], a3);
        }
        out[(row0 + r) * NCLS + c] = (a0 + a1) + (a2 + a3) + bfc[c];
    }
}

// ---------------------------------------------------------------------------
extern "C" void kernel_launch(void* const* d_in, const int* in_sizes, int n_in,
                              void* d_out, int out_size) {
    const float* features = (const float*)d_in[0];
    const int*   ids0     = (const int*)  d_in[1];
    const int*   ids1     = (const int*)  d_in[2];
    const int*   ids2     = (const int*)  d_in[3];
    const float* W2s      = (const float*)d_in[4];
    const float* b2s      = (const float*)d_in[5];
    const float* W2n      = (const float*)d_in[6];
    const float* b2n      = (const float*)d_in[7];
    const float* W1s      = (const float*)d_in[8];
    const float* b1s      = (const float*)d_in[9];
    const float* W1n      = (const float*)d_in[10];
    const float* b1n      = (const float*)d_in[11];
    const float* Wfc      = (const float*)d_in[12];
    const float* bfc      = (const float*)d_in[13];
    float* out = (float*)d_out;

    cudaFuncSetAttribute(gemm2_kernel,
                         cudaFuncAttributeMaxDynamicSharedMemorySize,
                         G_SMEM_BYTES);

    agg2_kernel<<<ROWS1, 128>>>(features, ids2);
    gemm2_kernel<<<dim3(ROWS1 / BM2, 2), 256, G_SMEM_BYTES>>>(
        features, ids1, W2s, W2n, b2s, b2n);
    head_gemm_kernel<<<dim3(BATCH / HBM, 2, 4), 256>>>(features, ids0, W1s, W1n);
    clf_kernel<<<BATCH / CRPB, 256>>>(b1s, b1n, Wfc, bfc, out);
}